// round 14
// baseline (speedup 1.0000x reference)
#include <cuda_runtime.h>
#include <cuda_bf16.h>
#include <cstdint>

#define EMBED 1024
#define HEADS 16
#define HDIM  64
#define LSEQ  1024
#define MAXB  4
#define MCH   32
#define OUTD  1024
#define PIF   3.14159265358979f

typedef unsigned long long u64;

// ================= helpers =================
__device__ __forceinline__ float frcp(float x) {
    float r; asm("rcp.approx.f32 %0, %1;" : "=f"(r) : "f"(x)); return r;
}
__device__ __forceinline__ u64 fma2(u64 a, u64 b, u64 c) {
    u64 d;
    asm("fma.rn.f32x2 %0, %1, %2, %3;" : "=l"(d) : "l"(a), "l"(b), "l"(c));
    return d;
}
__device__ __forceinline__ uint32_t smem_u32(const void* p) {
    uint32_t a;
    asm("{ .reg .u64 t; cvta.to.shared.u64 t, %1; cvt.u32.u64 %0, t; }" : "=r"(a) : "l"(p));
    return a;
}
__device__ __forceinline__ void mma16816(float* c, const unsigned* a, const unsigned* b) {
    asm volatile(
        "mma.sync.aligned.m16n8k16.row.col.f32.bf16.bf16.f32 "
        "{%0,%1,%2,%3}, {%4,%5,%6,%7}, {%8,%9}, {%0,%1,%2,%3};"
        : "+f"(c[0]), "+f"(c[1]), "+f"(c[2]), "+f"(c[3])
        : "r"(a[0]), "r"(a[1]), "r"(a[2]), "r"(a[3]), "r"(b[0]), "r"(b[1]));
}
__device__ __forceinline__ unsigned pack_hi(float x0, float x1) {
    __nv_bfloat162 h;
    h.x = __float2bfloat16(x0);
    h.y = __float2bfloat16(x1);
    return *(unsigned*)&h;
}
__device__ __forceinline__ unsigned pack_lo(float x0, float x1) {
    __nv_bfloat16 h0 = __float2bfloat16(x0);
    __nv_bfloat16 h1 = __float2bfloat16(x1);
    __nv_bfloat162 l;
    l.x = __float2bfloat16(x0 - __bfloat162float(h0));
    l.y = __float2bfloat16(x1 - __bfloat162float(h1));
    return *(unsigned*)&l;
}

// ================= scratch =================
__device__ float g_WqE[EMBED * HEADS];
__device__ float g_WkE[EMBED * HEADS];
__device__ float g_bqE[HEADS];
__device__ float g_SQ[MAXB * HEADS * LSEQ];
__device__ float g_SK[MAXB * HEADS * LSEQ];
__device__ unsigned g_skmax_bits;
__device__ float g_Spart[4 * MAXB * HEADS * MCH];
__device__ float g_P[(size_t)MAXB * 512 * EMBED];
__device__ float g_Tpart[4 * MAXB * HEADS * MCH * HDIM];

__device__ __align__(16) __nv_bfloat16 g_Psih[(size_t)MAXB * 512 * LSEQ];
__device__ __align__(16) __nv_bfloat16 g_Psil[(size_t)MAXB * 512 * LSEQ];
__device__ __align__(16) __nv_bfloat16 g_VTh[(size_t)MAXB * 1024 * 1024];
__device__ __align__(16) __nv_bfloat16 g_VTl[(size_t)MAXB * 1024 * 1024];
__device__ __align__(16) __nv_bfloat16 g_Phih[(size_t)MAXB * LSEQ * 512];
__device__ __align__(16) __nv_bfloat16 g_Phil[(size_t)MAXB * LSEQ * 512];
__device__ __align__(16) __nv_bfloat16 g_UTh[(size_t)MAXB * 1024 * 512];
__device__ __align__(16) __nv_bfloat16 g_UTl[(size_t)MAXB * 1024 * 512];

// ================= K0: prep = V transpose/split + effective weights ================
__global__ void __launch_bounds__(256) k_prep(const float* __restrict__ vin,
                                              const float* __restrict__ Wq,
                                              const float* __restrict__ Wk,
                                              const float* __restrict__ bq,
                                              const float* __restrict__ aw) {
    __shared__ float tsm[32][33];
    int bid = blockIdx.x;
    if (bid < 4096) {
        int cx = bid & 31, cy = (bid >> 5) & 31, b = bid >> 10;
        const float* in = vin + (size_t)b * 1024 * 1024;
        __nv_bfloat16* oh = g_VTh + (size_t)b * 1024 * 1024;
        __nv_bfloat16* ol = g_VTl + (size_t)b * 1024 * 1024;
        int r0 = cy * 32, c0 = cx * 32;
        int tx = threadIdx.x & 31, ty = threadIdx.x >> 5;
#pragma unroll
        for (int s = 0; s < 4; s++) {
            int r = ty + s * 8;
            tsm[r][tx] = in[(size_t)(r0 + r) * 1024 + c0 + tx];
        }
        __syncthreads();
#pragma unroll
        for (int s = 0; s < 4; s++) {
            int c = ty + s * 8;
            float x = tsm[tx][c];
            __nv_bfloat16 h = __float2bfloat16(x);
            size_t o = (size_t)(c0 + c) * 1024 + r0 + tx;
            oh[o] = h;
            ol[o] = __float2bfloat16(x - __bfloat162float(h));
        }
    } else {
        int t = (bid - 4096) * 256 + threadIdx.x;
        if (t == 0) g_skmax_bits = 0u;
        int side = t >> 14;
        int u = t & 16383;
        int e = u >> 4, n = u & 15;
        const float* W = side ? Wk : Wq;
        const float* w = aw + side * HDIM;
        float s = 0.f;
#pragma unroll 8
        for (int d = 0; d < HDIM; d++)
            s += W[(size_t)e * (HEADS * HDIM) + n * HDIM + d] * w[d];
        if (side) g_WkE[e * 16 + n] = s;
        else      g_WqE[e * 16 + n] = s;
        if (!side && e == 0) {
            float sb = 0.f;
#pragma unroll 8
            for (int d = 0; d < HDIM; d++) sb += bq[n * HDIM + d] * w[d];
            g_bqE[n] = sb;
        }
    }
}

// ================= K1: sq/sk — MLP-8 prefetch ======================================
#define PADF 1028
#define SQK_SMEM (16 * PADF * 4)
__global__ void __launch_bounds__(256) k_sqk(const float* __restrict__ qin,
                                             const float* __restrict__ kin) {
    extern __shared__ float sWEt[];
    __shared__ float sred[8];
    int side = blockIdx.y;
    const float* WE = side ? g_WkE : g_WqE;
    int tid = threadIdx.x;

    for (int idx = tid; idx < EMBED * HEADS; idx += 256) {
        int e = idx >> 4, n = idx & 15;
        sWEt[n * PADF + e] = WE[idx];
    }
    __syncthreads();

    int rl = tid >> 3;
    int p  = tid & 7;
    int row = blockIdx.x * 32 + rl;
    const float* xr = (side ? kin : qin) + (size_t)row * EMBED;

    u64 acc[16];
#pragma unroll
    for (int n = 0; n < 16; n++) acc[n] = 0ull;

    // 4 phases; each prefetches 8 independent float4 loads (MLP=8), then consumes.
    // Same per-accumulator FMA order as before (i = ph*8+q ascending) -> bit-identical.
#pragma unroll
    for (int ph = 0; ph < 4; ph++) {
        float4 xv[8];
#pragma unroll
        for (int q = 0; q < 8; q++)
            xv[q] = *(const float4*)(xr + ph * 256 + (q * 8 + p) * 4);
#pragma unroll
        for (int q = 0; q < 8; q++) {
            int e = ph * 256 + (q * 8 + p) * 4;
            u64 xlo, xhi;
            asm("mov.b64 %0, {%1, %2};" : "=l"(xlo) : "f"(xv[q].x), "f"(xv[q].y));
            asm("mov.b64 %0, {%1, %2};" : "=l"(xhi) : "f"(xv[q].z), "f"(xv[q].w));
#pragma unroll
            for (int n = 0; n < 16; n++) {
                float4 wv = *(const float4*)&sWEt[n * PADF + e];
                u64 wlo, whi;
                asm("mov.b64 %0, {%1, %2};" : "=l"(wlo) : "f"(wv.x), "f"(wv.y));
                asm("mov.b64 %0, {%1, %2};" : "=l"(whi) : "f"(wv.z), "f"(wv.w));
                acc[n] = fma2(xlo, wlo, acc[n]);
                acc[n] = fma2(xhi, whi, acc[n]);
            }
        }
    }

    float s[16];
#pragma unroll
    for (int n = 0; n < 16; n++) {
        float lo, hi;
        asm("mov.b64 {%0, %1}, %2;" : "=f"(lo), "=f"(hi) : "l"(acc[n]));
        s[n] = lo + hi;
    }
#pragma unroll
    for (int msk = 1; msk < 8; msk <<= 1)
#pragma unroll
        for (int n = 0; n < 16; n++)
            s[n] += __shfl_xor_sync(0xffffffffu, s[n], msk);

    int n0 = p * 2;
    float v0 = s[n0], v1 = s[n0 + 1];
    if (!side) { v0 += g_bqE[n0]; v1 += g_bqE[n0 + 1]; }
    int b = row >> 10, ii = row & 1023;
    float* dst = side ? g_SK : g_SQ;
    dst[((b * 16 + n0) << 10) + ii]     = v0;
    dst[((b * 16 + n0 + 1) << 10) + ii] = v1;

    if (side) {
        float a = fmaxf(fabsf(v0), fabsf(v1));
        int lane = tid & 31, wid = tid >> 5;
#pragma unroll
        for (int o = 16; o; o >>= 1) a = fmaxf(a, __shfl_xor_sync(0xffffffffu, a, o));
        if (lane == 0) sred[wid] = a;
        __syncthreads();
        if (tid == 0) {
            float mx = 0.f;
#pragma unroll
            for (int w2 = 0; w2 < 8; w2++) mx = fmaxf(mx, sred[w2]);
            atomicMax(&g_skmax_bits, __float_as_uint(mx));
        }
    }
}

// ---- inline Chebyshev nodes ----
#define CHEB_LOCAL(yn, wb, tid) do { \
    if ((tid) < MCH) { \
        float smax = __uint_as_float(g_skmax_bits); \
        float Y = smax * 1.0005f + 1e-6f; \
        float th = (2.f * (tid) + 1.f) * (PIF / 64.f); \
        (yn)[tid] = Y * cosf(th); \
        if (wb) ((float*)(wb))[tid] = (((tid) & 1) ? -sinf(th) : sinf(th)); \
    } \
} while (0)

// ================= K2: Psi + S partials =================
__global__ void __launch_bounds__(256) k_psimat() {
    __shared__ float sp[256][33];
    __shared__ float colsum[8][32];
    __shared__ float yn[MCH], wb[MCH];
    int bn = blockIdx.y;
    int b = bn >> 4, n = bn & 15;
    int jc = blockIdx.x;
    int j0 = jc * 256;
    int tid = threadIdx.x;
    CHEB_LOCAL(yn, wb, tid);
    __syncthreads();

    {
        float y = g_SK[(bn << 10) + j0 + tid];
        float t[MCH];
        float den = 0.f;
#pragma unroll
        for (int m = 0; m < MCH; m++) {
            float d = y - yn[m];
            d = (fabsf(d) < 1e-12f) ? 1e-12f : d;
            t[m] = wb[m] * frcp(d);
            den += t[m];
        }
        float ri = frcp(den);
#pragma unroll
        for (int m = 0; m < MCH; m++) sp[tid][m] = t[m] * ri;
    }
    __syncthreads();

    {
        int m = tid & 31, seg = tid >> 5;
        float s = 0.f;
#pragma unroll 8
        for (int r = 0; r < 32; r++) s += sp[seg * 32 + r][m];
        colsum[seg][m] = s;
    }
    __syncthreads();
    if (tid < 32) {
        float t = 0.f;
#pragma unroll
        for (int s8 = 0; s8 < 8; s8++) t += colsum[s8][tid];
        g_Spart[(jc * 64 + bn) * MCH + tid] = t;
    }

    int r  = tid >> 3;
    int cg = (tid & 7) * 32;
    size_t base = (((size_t)b * 512) + n * 32 + r) * LSEQ + j0 + cg;
#pragma unroll
    for (int q8 = 0; q8 < 4; q8++) {
        unsigned hh[4], ll[4];
#pragma unroll
        for (int p2 = 0; p2 < 4; p2++) {
            float x0 = sp[cg + q8 * 8 + p2 * 2][r];
            float x1 = sp[cg + q8 * 8 + p2 * 2 + 1][r];
            hh[p2] = pack_hi(x0, x1);
            ll[p2] = pack_lo(x0, x1);
        }
        *(uint4*)(g_Psih + base + q8 * 8) = *(uint4*)hh;
        *(uint4*)(g_Psil + base + q8 * 8) = *(uint4*)ll;
    }
}

// ================= HMMA bf16-split GEMM — 3-stage cp.async, mt-interleaved ========
#define BKC 64
#define STRD 72
#define TEN_ELE (128 * STRD)
#define STAGE_ELE (4 * TEN_ELE)
#define NSTAGE 3
#define MMA_SMEM (NSTAGE * STAGE_ELE * 2)

template <bool BIAS>
__global__ void __launch_bounds__(256) k_gemm_mma(
    const __nv_bfloat16* __restrict__ Ah, const __nv_bfloat16* __restrict__ Al,
    const __nv_bfloat16* __restrict__ Bh, const __nv_bfloat16* __restrict__ Bl,
    const float* __restrict__ bias, float* __restrict__ C,
    int K, size_t sA, size_t sB, size_t sC)
{
    extern __shared__ __nv_bfloat16 sm[];
    uint32_t sbase = smem_u32(sm);

    int tid = threadIdx.x, lane = tid & 31, wid = tid >> 5;
    int wm = wid >> 1, wn = wid & 1;
    int m0 = blockIdx.y * 128, n0 = blockIdx.x * 128;

    const __nv_bfloat16* srcs[4] = {
        Ah + blockIdx.z * sA + (size_t)m0 * K,
        Al + blockIdx.z * sA + (size_t)m0 * K,
        Bh + blockIdx.z * sB + (size_t)n0 * K,
        Bl + blockIdx.z * sB + (size_t)n0 * K };
    C += blockIdx.z * sC;

    int g = lane >> 2, tg = lane & 3;
    const int nch = K >> 6;

    float acc[2][8][4];
#pragma unroll
    for (int a = 0; a < 2; a++)
#pragma unroll
        for (int b = 0; b < 8; b++)
#pragma unroll
            for (int c = 0; c < 4; c++) acc[a][b][c] = 0.f;

    auto load_stage = [&](int st, int c) {
#pragma unroll
        for (int t = 0; t < 4; t++) {
#pragma unroll
            for (int s = 0; s < 4; s++) {
                int i = tid + s * 256;
                int row = i >> 3, ch = (i & 7) * 8;
                const void* gp = srcs[t] + (size_t)row * K + c * BKC + ch;
                uint32_t dp = sbase + (uint32_t)(st * STAGE_ELE + t * TEN_ELE + row * STRD + ch) * 2;
                asm volatile("cp.async.cg.shared.global [%0], [%1], 16;" :: "r"(dp), "l"(gp));
            }
        }
        asm volatile("cp.async.commit_group;");
    };

    load_stage(0, 0);
    if (nch > 1) load_stage(1, 1);

    for (int c = 0; c < nch; c++) {
        if (c + 1 < nch) {
            asm volatile("cp.async.wait_group 1;");
        } else {
            asm volatile("cp.async.wait_group 0;");
        }
        __syncthreads();

        if (c + 2 < nch) load_stage((c + 2) % NSTAGE, c + 2);

        const __nv_bfloat16* sAh = sm + (size_t)(c % NSTAGE) * STAGE_ELE;
        const __nv_bfloat16* sAl = sAh + TEN_ELE;
        const __nv_bfloat16* sBh = sAh + 2 * TEN_ELE;
        const __nv_bfloat16* sBl = sAh + 3 * TEN_ELE;

#pragma unroll
        for (int ks = 0; ks < 4; ks++) {
            int k0 = ks * 16 + tg * 2;
            unsigned ah[2][4], al[2][4];
#pragma unroll
            for (int mt = 0; mt < 2; mt++) {
                int rb = wm * 32 + mt * 16 + g;
                ah[mt][0] = *(const unsigned*)(sAh + rb * STRD + k0);
                ah[mt][1] = *(const unsigned*)(sAh + (rb + 8) * STRD + k0);
                ah[mt][2] = *(const unsigned*)(sAh + rb * STRD + k0 + 8);
                ah[mt][3] = *(const unsigned*)(sAh + (rb + 8) * STRD + k0 + 8);
                al[mt][0] = *(const unsigned*)(sAl + rb * STRD + k0);
                al[mt][1] = *(const unsigned*)(sAl + (rb + 8) * STRD + k0);
                al[mt][2] = *(const unsigned*)(sAl + rb * STRD + k0 + 8);
                al[mt][3] = *(const unsigned*)(sAl + (rb + 8) * STRD + k0 + 8);
            }
#pragma unroll
            for (int nt = 0; nt < 8; nt++) {
                int cb = wn * 64 + nt * 8 + g;
                unsigned bh[2], bl[2];
                bh[0] = *(const unsigned*)(sBh + cb * STRD + k0);
                bh[1] = *(const unsigned*)(sBh + cb * STRD + k0 + 8);
                bl[0] = *(const unsigned*)(sBl + cb * STRD + k0);
                bl[1] = *(const unsigned*)(sBl + cb * STRD + k0 + 8);
                mma16816(acc[0][nt], ah[0], bh);
                mma16816(acc[1][nt], ah[1], bh);
                mma16816(acc[0][nt], ah[0], bl);
                mma16816(acc[1][nt], ah[1], bl);
                mma16816(acc[0][nt], al[0], bh);
                mma16816(acc[1][nt], al[1], bh);
            }
        }
        __syncthreads();
    }

#pragma unroll
    for (int mt = 0; mt < 2; mt++) {
        int row0 = m0 + wm * 32 + mt * 16 + g;
#pragma unroll
        for (int nt = 0; nt < 8; nt++) {
            int col = n0 + wn * 64 + nt * 8 + tg * 2;
            float2 v0, v1;
            v0.x = acc[mt][nt][0]; v0.y = acc[mt][nt][1];
            v1.x = acc[mt][nt][2]; v1.y = acc[mt][nt][3];
            if (BIAS) {
                float2 bv = *(const float2*)(bias + col);
                v0.x += bv.x; v0.y += bv.y;
                v1.x += bv.x; v1.y += bv.y;
            }
            *(float2*)(C + (size_t)row0 * 1024 + col) = v0;
            *(float2*)(C + (size_t)(row0 + 8) * 1024 + col) = v1;
        }
    }
}

// ================= K4: T partials — grid (4 echunks, 64 bn), conflict-free ========
__global__ void __launch_bounds__(256) k_Tp(const float* __restrict__ Wv) {
    __shared__ float sp[32 * 68];
    __shared__ float sw[64 * 64];
    int ec = blockIdx.x;
    int bn = blockIdx.y;
    int b = bn >> 4, n = bn & 15;
    int tid = threadIdx.x;
    int m = tid >> 3;
    int p = tid & 7;

    const float* P = g_P + ((size_t)b * 512 + n * 32) * EMBED + ec * 256;

    float acc[8];
#pragma unroll
    for (int c = 0; c < 8; c++) acc[c] = 0.f;

    for (int e0 = 0; e0 < 256; e0 += 64) {
        __syncthreads();
#pragma unroll
        for (int s = 0; s < 2; s++) {
            int f4 = tid + s * 256;
            int row = f4 >> 4, c4 = (f4 & 15) * 4;
            *(float4*)&sp[row * 68 + c4] = *(const float4*)(P + (size_t)row * EMBED + e0 + c4);
        }
#pragma unroll
        for (int s = 0; s < 4; s++) {
            int f4 = tid + s * 256;
            int row = f4 >> 4, c4 = (f4 & 15) * 4;
            *(float4*)&sw[row * 64 + c4] =
                *(const float4*)(Wv + (size_t)(ec * 256 + e0 + row) * (HEADS * HDIM) + n * 64 + c4);
        }
        __syncthreads();

#pragma unroll 4
        for (int e = 0; e < 64; e++) {
            float pv = sp[m * 68 + e];
            float4 w0 = *(const float4*)&sw[e * 64 + 4 * p];
            float4 w1 = *(const float4*)&sw[e * 64 + 32 + 4 * p];
            acc[0] += pv * w0.x; acc[1] += pv * w0.y;
            acc[2] += pv * w0.z; acc[3] += pv * w0.w;
            acc[4] += pv * w1.x; acc[5] += pv * w1.y;
            acc[6] += pv * w1.z; acc[7] += pv * w1.w;
        }
    }

    float* Tp = g_Tpart + (((size_t)ec * 64 + bn) * 32 + m) * 64;
    float4 o0, o1;
    o0.x = acc[0]; o0.y = acc[1]; o0.z = acc[2]; o0.w = acc[3];
    o1.x = acc[4]; o1.y = acc[5]; o1.z = acc[6]; o1.w = acc[7];
    *(float4*)(Tp + 4 * p) = o0;
    *(float4*)(Tp + 32 + 4 * p) = o1;
}

// ================= K5: U (sums T partials) + transpose/bf16 split -> UT ===========
#define KU_SMEM ((32 * 68 + 16 * 256 + 32 * 264) * 4)
__global__ void __launch_bounds__(256) k_U(const float* __restrict__ Wp) {
    extern __shared__ float us[];
    float* sT = us;
    float* sW = us + 32 * 68;
    float* sO = us + 32 * 68 + 16 * 256;

    int bn = blockIdx.y;
    int b = bn >> 4, n = bn & 15;
    int c0 = blockIdx.x * 256;
    int tid = threadIdx.x;
    int m = tid >> 3;
    int p = tid & 7;
    int dq4 = 4 * p;

#pragma unroll
    for (int s = 0; s < 2; s++) {
        int f4 = tid + s * 256;
        int row = f4 >> 4, c4 = (f4 & 15) * 4;
        size_t off = ((size_t)bn * 32 + row) * 64 + c4;
        float4 a0 = *(const float4*)(g_Tpart + off);
        float4 a1 = *(const float4*)(g_Tpart + (size_t)1 * 64 * 32 * 64 + off);
        float4 a2 = *(const float4*)(g_Tpart + (size_t)2 * 64 * 32 * 64 + off);
        float4 a3 = *(const float4*)(g_Tpart + (size_t)3 * 64 * 32 * 64 + off);
        float4 o;
        o.x = (a0.x + a1.x) + (a2.x + a3.x);
        o.y = (a0.y + a1.y) + (a2.y + a3.y);
        o.z = (a0.z + a1.z) + (a2.z + a3.z);
        o.w = (a0.w + a1.w) + (a2.w + a3.w);
        *(float4*)&sT[row * 68 + c4] = o;
    }

    float acc[32];
#pragma unroll
    for (int c = 0; c < 32; c++) acc[c] = 0.f;

    for (int dt = 0; dt < 4; dt++) {
        __syncthreads();
#pragma unroll
        for (int s = 0; s < 4; s++) {
            int f4 = tid + s * 256;
            int row = f4 >> 6, c4 = (f4 & 63) * 4;
            *(float4*)&sW[row * 256 + c4] =
                *(const float4*)(Wp + (size_t)(n * 64 + dt * 16 + row) * OUTD + c0 + c4);
        }
        __syncthreads();

#pragma unroll
        for (int d = 0; d < 16; d++) {
            float t = sT[m * 68 + dt * 16 + d];
#pragma unroll
            for (int k = 0; k < 8; k++) {
                float4 w = *(const float4*)&sW[d * 256 + k * 32 + dq4];
                acc[k * 4 + 0] += t * w.x;
                acc[k * 4 + 1] += t * w.y;
                acc[k * 4 + 2] += t * w.z;
                acc[k * 4 + 3] += t * w.w;
            }
        }
    }

#pragma unroll
    for (int k = 0; k < 8; k++) {
        float4 o;
        o.x = acc[k * 4 + 0]; o.y = acc[k * 4 + 1];
        o.z = acc[k * 4 + 2]; o.w = acc[k * 4 + 3];
        *(float4*)&sO[m * 264 + k * 32 + dq4] = o;
    }
    __syncthreads();

    {
        int o = c0 + tid;
        size_t rowbase = (((size_t)b * 1024) + o) * 512 + n * 32;
        unsigned hh[16], ll[16];
#pragma unroll
        for (int mm = 0; mm < 16; mm++) {
            float x0 = sO[(2 * mm) * 264 + tid];
            float x1 = sO[(2 * mm + 1) * 264 + tid];
            hh[mm] = pack_hi(x0, x1);
            ll[mm] = pack_lo(x0, x1);
        }
#pragma unroll
        for (int q = 0; q < 4; q++) {
            *(uint4*)(g_UTh + rowbase + q * 8) = *(uint4*)&hh[q * 4];
            *(uint4*)(g_UTl + rowbase + q * 8) = *(uint4*)&ll[q * 4];
        }
    }
}

// ================= K6: Phi~ (bf16 hi/lo, [i][nm]) =================
__global__ void __launch_bounds__(256) k_phiq() {
    __shared__ float syn[MCH];
    __shared__ float sS[16][MCH];
    int b = blockIdx.y;
    int tid = threadIdx.x;
    int n = tid & 15;
    int ir = tid >> 4;
    int i = blockIdx.x * 16 + ir;

    CHEB_LOCAL(syn, (float*)0, tid);
    for (int t = tid; t < 16 * MCH; t += 256) {
        int hn = t >> 5, m = t & 31;
        int bn = b * 16 + hn;
        float s = g_Spart[(0 * 64 + bn) * MCH + m] + g_Spart[(1 * 64 + bn) * MCH + m]
                + g_Spart[(2 * 64 + bn) * MCH + m] + g_Spart[(3 * 64 + bn) * MCH + m];
        sS[hn][m] = s;
    }
    __syncthreads();

    float sq = g_SQ[((b * 16 + n) << 10) + i];
    float phi[MCH];
    float den = 0.f;
#pragma unroll
    for (int m = 0; m < MCH; m++) {
        float u = __expf(2.f * (sq + syn[m]));
        float t = (u - 1.f) * frcp(u + 1.f);
        float p = __expf(t);
        phi[m] = p;
        den += p * sS[n][m];
    }
    float inv = frcp(den);

    size_t base = ((((size_t)b << 10) + i) * 512) + n * 32;
#pragma unroll
    for (int q8 = 0; q8 < 4; q8++) {
        unsigned hh[4], ll[4];
#pragma unroll
        for (int p2 = 0; p2 < 4; p2++) {
            float x0 = phi[q8 * 8 + p2 * 2]     * inv;
            float x1 = phi[q8 * 8 + p2 * 2 + 1] * inv;
            hh[p2] = pack_hi(x0, x1);
            ll[p2] = pack_lo(x0, x1);
        }
        *(uint4*)(g_Phih + base + q8 * 8) = *(uint4*)hh;
        *(uint4*)(g_Phil + base + q8 * 8) = *(uint4*)ll;
    }
}

// ================= K7: layernorm =================
__global__ void __launch_bounds__(256) k_ln(float* __restrict__ y,
                                            const float* __restrict__ gamma,
                                            const float* __restrict__ beta) {
    int row = blockIdx.x, tid = threadIdx.x;
    float4* yp = (float4*)(y + (size_t)row * 1024);
    float4 v = yp[tid];
    float s  = v.x + v.y + v.z + v.w;
    float ss = v.x * v.x + v.y * v.y + v.z * v.z + v.w * v.w;

    __shared__ float red[16];
    int lane = tid & 31, wid = tid >> 5;
#pragma unroll
    for (int o = 16; o; o >>= 1) {
        s  += __shfl_xor_sync(0xffffffffu, s,  o);
        ss += __shfl_xor_sync(0xffffffffu, ss, o);
    }
    if (lane == 0) { red[wid] = s; red[wid + 8] = ss; }
    __syncthreads();
    if (tid == 0) {
        float S = 0.f, SS = 0.f;
        for (int w = 0; w < 8; w++) { S += red[w]; SS += red[w + 8]; }
        red[0] = S; red[1] = SS;
    }
    __syncthreads();
    float mean = red[0] * (1.0f / 1024.0f);
    float var  = red[1] * (1.0f / 1024.0f) - mean * mean;
    float rr = rsqrtf(var + 1e-6f);

    float4 g  = ((const float4*)gamma)[tid];
    float4 bb = ((const float4*)beta)[tid];
    float4 o;
    o.x = (v.x - mean) * rr * g.x + bb.x;
    o.y = (v.y - mean) * rr * g.y + bb.y;
    o.z = (v.z - mean) * rr * g.z + bb.z;
    o.w = (v.w - mean) * rr * g.w + bb.w;
    yp[tid] = o;
}

// ================= launcher =================
extern "C" void kernel_launch(void* const* d_in, const int* in_sizes, int n_in,
                              void* d_out, int out_size) {
    (void)n_in; (void)out_size;
    const float* k_in  = (const float*)d_in[0];
    const float* q_in  = (const float*)d_in[1];
    const float* v_in  = (const float*)d_in[2];
    const float* Wq    = (const float*)d_in[3];
    const float* bq    = (const float*)d_in[4];
    const float* Wk    = (const float*)d_in[5];
    const float* Wv    = (const float*)d_in[6];
    const float* Wp    = (const float*)d_in[7];
    const float* bp    = (const float*)d_in[8];
    const float* aw    = (const float*)d_in[9];
    const float* gamma = (const float*)d_in[10];
    const float* beta  = (const float*)d_in[11];
    float* out = (float*)d_out;

    int B = in_sizes[0] / (LSEQ * EMBED);   // 4
    int M = B * LSEQ;                        // 4096

    float* p_P = nullptr;
    __nv_bfloat16 *p_Psih, *p_Psil, *p_VTh, *p_VTl, *p_Phih, *p_Phil, *p_UTh, *p_UTl;
    cudaGetSymbolAddress((void**)&p_P,    g_P);
    cudaGetSymbolAddress((void**)&p_Psih, g_Psih);
    cudaGetSymbolAddress((void**)&p_Psil, g_Psil);
    cudaGetSymbolAddress((void**)&p_VTh,  g_VTh);
    cudaGetSymbolAddress((void**)&p_VTl,  g_VTl);
    cudaGetSymbolAddress((void**)&p_Phih, g_Phih);
    cudaGetSymbolAddress((void**)&p_Phil, g_Phil);
    cudaGetSymbolAddress((void**)&p_UTh,  g_UTh);
    cudaGetSymbolAddress((void**)&p_UTl,  g_UTl);

    cudaFuncSetAttribute(k_sqk, cudaFuncAttributeMaxDynamicSharedMemorySize, SQK_SMEM);
    cudaFuncSetAttribute(k_U,   cudaFuncAttributeMaxDynamicSharedMemorySize, KU_SMEM);
    cudaFuncSetAttribute(k_gemm_mma<false>, cudaFuncAttributeMaxDynamicSharedMemorySize, MMA_SMEM);
    cudaFuncSetAttribute(k_gemm_mma<true>,  cudaFuncAttributeMaxDynamicSharedMemorySize, MMA_SMEM);

    k_prep<<<4096 + 128, 256>>>(v_in, Wq, Wk, bq, aw);                  // 0
    k_sqk<<<dim3(M / 32, 2), 256, SQK_SMEM>>>(q_in, k_in);              // 1
    k_psimat<<<dim3(LSEQ / 256, B * HEADS), 256>>>();                   // 2
    // P[b] (512 x 1024) = Psi_b @ v_b   (HMMA, K = 1024)               // 3 <- profiled
    k_gemm_mma<false><<<dim3(8, 4, B), 256, MMA_SMEM>>>(
        p_Psih, p_Psil, p_VTh, p_VTl, nullptr, p_P,
        1024, (size_t)512 * 1024, (size_t)1024 * 1024, (size_t)512 * 1024);
    k_phiq<<<dim3(LSEQ / 16, B), 256>>>();
    k_Tp<<<dim3(4, B * HEADS), 256>>>(Wv);
    k_U<<<dim3(4, B * HEADS), 256, KU_SMEM>>>(Wp);
    // out[b] (1024 x 1024) = Phi_b @ U_b + bp   (HMMA, K = 512)
    k_gemm_mma<true><<<dim3(8, 8, B), 256, MMA_SMEM>>>(
        p_Phih, p_Phil, p_UTh, p_UTl, bp, out,
        512, (size_t)1024 * 512, (size_t)1024 * 512, (size_t)1024 * 1024);
    k_ln<<<M, 256>>>(out, gamma, beta);
}

// round 15
// speedup vs baseline: 1.0489x; 1.0489x over previous
#include <cuda_runtime.h>
#include <cuda_bf16.h>
#include <cstdint>

#define EMBED 1024
#define HEADS 16
#define HDIM  64
#define LSEQ  1024
#define MAXB  4
#define MCH   32
#define OUTD  1024
#define PIF   3.14159265358979f

typedef unsigned long long u64;

// ================= helpers =================
__device__ __forceinline__ float frcp(float x) {
    float r; asm("rcp.approx.f32 %0, %1;" : "=f"(r) : "f"(x)); return r;
}
__device__ __forceinline__ u64 fma2(u64 a, u64 b, u64 c) {
    u64 d;
    asm("fma.rn.f32x2 %0, %1, %2, %3;" : "=l"(d) : "l"(a), "l"(b), "l"(c));
    return d;
}
__device__ __forceinline__ uint32_t smem_u32(const void* p) {
    uint32_t a;
    asm("{ .reg .u64 t; cvta.to.shared.u64 t, %1; cvt.u32.u64 %0, t; }" : "=r"(a) : "l"(p));
    return a;
}
__device__ __forceinline__ void mma16816(float* c, const unsigned* a, const unsigned* b) {
    asm volatile(
        "mma.sync.aligned.m16n8k16.row.col.f32.bf16.bf16.f32 "
        "{%0,%1,%2,%3}, {%4,%5,%6,%7}, {%8,%9}, {%0,%1,%2,%3};"
        : "+f"(c[0]), "+f"(c[1]), "+f"(c[2]), "+f"(c[3])
        : "r"(a[0]), "r"(a[1]), "r"(a[2]), "r"(a[3]), "r"(b[0]), "r"(b[1]));
}
__device__ __forceinline__ unsigned pack_hi(float x0, float x1) {
    __nv_bfloat162 h;
    h.x = __float2bfloat16(x0);
    h.y = __float2bfloat16(x1);
    return *(unsigned*)&h;
}
__device__ __forceinline__ unsigned pack_lo(float x0, float x1) {
    __nv_bfloat16 h0 = __float2bfloat16(x0);
    __nv_bfloat16 h1 = __float2bfloat16(x1);
    __nv_bfloat162 l;
    l.x = __float2bfloat16(x0 - __bfloat162float(h0));
    l.y = __float2bfloat16(x1 - __bfloat162float(h1));
    return *(unsigned*)&l;
}

// ================= scratch =================
__device__ float g_WqE[EMBED * HEADS];
__device__ float g_WkE[EMBED * HEADS];
__device__ float g_bqE[HEADS];
__device__ float g_SQ[MAXB * HEADS * LSEQ];
__device__ float g_SK[MAXB * HEADS * LSEQ];
__device__ unsigned g_skmax_bits;
__device__ float g_Spart[4 * MAXB * HEADS * MCH];
__device__ float g_P[(size_t)MAXB * 512 * EMBED];
__device__ float g_Tpart[4 * MAXB * HEADS * MCH * HDIM];   // [ec][bn][m][d]

__device__ __align__(16) __nv_bfloat16 g_Psih[(size_t)MAXB * 512 * LSEQ];
__device__ __align__(16) __nv_bfloat16 g_Psil[(size_t)MAXB * 512 * LSEQ];
__device__ __align__(16) __nv_bfloat16 g_VTh[(size_t)MAXB * 1024 * 1024];
__device__ __align__(16) __nv_bfloat16 g_VTl[(size_t)MAXB * 1024 * 1024];
__device__ __align__(16) __nv_bfloat16 g_Phih[(size_t)MAXB * LSEQ * 512];
__device__ __align__(16) __nv_bfloat16 g_Phil[(size_t)MAXB * LSEQ * 512];
__device__ __align__(16) __nv_bfloat16 g_UTh[(size_t)MAXB * 1024 * 512];
__device__ __align__(16) __nv_bfloat16 g_UTl[(size_t)MAXB * 1024 * 512];

// ================= K0a: effective weights =================
__global__ void k_weff(const float* __restrict__ Wq, const float* __restrict__ Wk,
                       const float* __restrict__ bq, const float* __restrict__ aw) {
    int t = blockIdx.x * blockDim.x + threadIdx.x;
    if (t == 0) g_skmax_bits = 0u;
    int side = t >> 14;
    int u = t & 16383;
    int e = u >> 4, n = u & 15;
    const float* W = side ? Wk : Wq;
    const float* w = aw + side * HDIM;
    float s = 0.f;
#pragma unroll 8
    for (int d = 0; d < HDIM; d++)
        s += W[(size_t)e * (HEADS * HDIM) + n * HDIM + d] * w[d];
    if (side) g_WkE[e * 16 + n] = s;
    else      g_WqE[e * 16 + n] = s;
    if (!side && e == 0) {
        float sb = 0.f;
#pragma unroll 8
        for (int d = 0; d < HDIM; d++) sb += bq[n * HDIM + d] * w[d];
        g_bqE[n] = sb;
    }
}

// ================= K0b: V transpose + bf16 split (half grid per launch) ===========
__global__ void __launch_bounds__(256) k_prepv(const float* __restrict__ vin, int half) {
    __shared__ float tsm[32][33];
    int cx = blockIdx.x, cy = blockIdx.y + half * 16, b = blockIdx.z;
    const float* in = vin + (size_t)b * 1024 * 1024;
    __nv_bfloat16* oh = g_VTh + (size_t)b * 1024 * 1024;
    __nv_bfloat16* ol = g_VTl + (size_t)b * 1024 * 1024;
    int r0 = cy * 32, c0 = cx * 32;
    int tx = threadIdx.x & 31, ty = threadIdx.x >> 5;
#pragma unroll
    for (int s = 0; s < 4; s++) {
        int r = ty + s * 8;
        tsm[r][tx] = in[(size_t)(r0 + r) * 1024 + c0 + tx];
    }
    __syncthreads();
#pragma unroll
    for (int s = 0; s < 4; s++) {
        int c = ty + s * 8;
        float x = tsm[tx][c];
        __nv_bfloat16 h = __float2bfloat16(x);
        size_t o = (size_t)(c0 + c) * 1024 + r0 + tx;
        oh[o] = h;
        ol[o] = __float2bfloat16(x - __bfloat162float(h));
    }
}

// ================= K1: sq/sk (PROFILED at launch index 3; unroll 8 for MLP) =======
#define PADF 1028
#define SQK_SMEM (16 * PADF * 4)
__global__ void __launch_bounds__(256) k_sqk(const float* __restrict__ qin,
                                             const float* __restrict__ kin) {
    extern __shared__ float sWEt[];
    __shared__ float sred[8];
    int side = blockIdx.y;
    const float* WE = side ? g_WkE : g_WqE;
    int tid = threadIdx.x;

    for (int idx = tid; idx < EMBED * HEADS; idx += 256) {
        int e = idx >> 4, n = idx & 15;
        sWEt[n * PADF + e] = WE[idx];
    }
    __syncthreads();

    int rl = tid >> 3;
    int p  = tid & 7;
    int row = blockIdx.x * 32 + rl;
    const float* xr = (side ? kin : qin) + (size_t)row * EMBED;

    u64 acc[16];
#pragma unroll
    for (int n = 0; n < 16; n++) acc[n] = 0ull;

#pragma unroll 8
    for (int i = 0; i < 32; i++) {
        int e = (i * 8 + p) * 4;
        float4 xv = *(const float4*)(xr + e);
        u64 xlo, xhi;
        asm("mov.b64 %0, {%1, %2};" : "=l"(xlo) : "f"(xv.x), "f"(xv.y));
        asm("mov.b64 %0, {%1, %2};" : "=l"(xhi) : "f"(xv.z), "f"(xv.w));
#pragma unroll
        for (int n = 0; n < 16; n++) {
            float4 wv = *(const float4*)&sWEt[n * PADF + e];
            u64 wlo, whi;
            asm("mov.b64 %0, {%1, %2};" : "=l"(wlo) : "f"(wv.x), "f"(wv.y));
            asm("mov.b64 %0, {%1, %2};" : "=l"(whi) : "f"(wv.z), "f"(wv.w));
            acc[n] = fma2(xlo, wlo, acc[n]);
            acc[n] = fma2(xhi, whi, acc[n]);
        }
    }

    float s[16];
#pragma unroll
    for (int n = 0; n < 16; n++) {
        float lo, hi;
        asm("mov.b64 {%0, %1}, %2;" : "=f"(lo), "=f"(hi) : "l"(acc[n]));
        s[n] = lo + hi;
    }
#pragma unroll
    for (int msk = 1; msk < 8; msk <<= 1)
#pragma unroll
        for (int n = 0; n < 16; n++)
            s[n] += __shfl_xor_sync(0xffffffffu, s[n], msk);

    int n0 = p * 2;
    float v0 = s[n0], v1 = s[n0 + 1];
    if (!side) { v0 += g_bqE[n0]; v1 += g_bqE[n0 + 1]; }
    int b = row >> 10, ii = row & 1023;
    float* dst = side ? g_SK : g_SQ;
    dst[((b * 16 + n0) << 10) + ii]     = v0;
    dst[((b * 16 + n0 + 1) << 10) + ii] = v1;

    if (side) {
        float a = fmaxf(fabsf(v0), fabsf(v1));
        int lane = tid & 31, wid = tid >> 5;
#pragma unroll
        for (int o = 16; o; o >>= 1) a = fmaxf(a, __shfl_xor_sync(0xffffffffu, a, o));
        if (lane == 0) sred[wid] = a;
        __syncthreads();
        if (tid == 0) {
            float mx = 0.f;
#pragma unroll
            for (int w2 = 0; w2 < 8; w2++) mx = fmaxf(mx, sred[w2]);
            atomicMax(&g_skmax_bits, __float_as_uint(mx));
        }
    }
}

// ---- inline Chebyshev nodes ----
#define CHEB_LOCAL(yn, wb, tid) do { \
    if ((tid) < MCH) { \
        float smax = __uint_as_float(g_skmax_bits); \
        float Y = smax * 1.0005f + 1e-6f; \
        float th = (2.f * (tid) + 1.f) * (PIF / 64.f); \
        (yn)[tid] = Y * cosf(th); \
        if (wb) ((float*)(wb))[tid] = (((tid) & 1) ? -sinf(th) : sinf(th)); \
    } \
} while (0)

// ================= K2: Psi + S partials =================
__global__ void __launch_bounds__(256) k_psimat() {
    __shared__ float sp[256][33];
    __shared__ float colsum[8][32];
    __shared__ float yn[MCH], wb[MCH];
    int bn = blockIdx.y;
    int b = bn >> 4, n = bn & 15;
    int jc = blockIdx.x;
    int j0 = jc * 256;
    int tid = threadIdx.x;
    CHEB_LOCAL(yn, wb, tid);
    __syncthreads();

    {
        float y = g_SK[(bn << 10) + j0 + tid];
        float t[MCH];
        float den = 0.f;
#pragma unroll
        for (int m = 0; m < MCH; m++) {
            float d = y - yn[m];
            d = (fabsf(d) < 1e-12f) ? 1e-12f : d;
            t[m] = wb[m] * frcp(d);
            den += t[m];
        }
        float ri = frcp(den);
#pragma unroll
        for (int m = 0; m < MCH; m++) sp[tid][m] = t[m] * ri;
    }
    __syncthreads();

    {
        int m = tid & 31, seg = tid >> 5;
        float s = 0.f;
#pragma unroll 8
        for (int r = 0; r < 32; r++) s += sp[seg * 32 + r][m];
        colsum[seg][m] = s;
    }
    __syncthreads();
    if (tid < 32) {
        float t = 0.f;
#pragma unroll
        for (int s8 = 0; s8 < 8; s8++) t += colsum[s8][tid];
        g_Spart[(jc * 64 + bn) * MCH + tid] = t;
    }

    int r  = tid >> 3;
    int cg = (tid & 7) * 32;
    size_t base = (((size_t)b * 512) + n * 32 + r) * LSEQ + j0 + cg;
#pragma unroll
    for (int q8 = 0; q8 < 4; q8++) {
        unsigned hh[4], ll[4];
#pragma unroll
        for (int p2 = 0; p2 < 4; p2++) {
            float x0 = sp[cg + q8 * 8 + p2 * 2][r];
            float x1 = sp[cg + q8 * 8 + p2 * 2 + 1][r];
            hh[p2] = pack_hi(x0, x1);
            ll[p2] = pack_lo(x0, x1);
        }
        *(uint4*)(g_Psih + base + q8 * 8) = *(uint4*)hh;
        *(uint4*)(g_Psil + base + q8 * 8) = *(uint4*)ll;
    }
}

// ================= HMMA bf16-split GEMM — 3-stage cp.async ========================
#define BKC 64
#define STRD 72
#define TEN_ELE (128 * STRD)
#define STAGE_ELE (4 * TEN_ELE)
#define NSTAGE 3
#define MMA_SMEM (NSTAGE * STAGE_ELE * 2)

template <bool BIAS>
__global__ void __launch_bounds__(256) k_gemm_mma(
    const __nv_bfloat16* __restrict__ Ah, const __nv_bfloat16* __restrict__ Al,
    const __nv_bfloat16* __restrict__ Bh, const __nv_bfloat16* __restrict__ Bl,
    const float* __restrict__ bias, float* __restrict__ C,
    int K, size_t sA, size_t sB, size_t sC)
{
    extern __shared__ __nv_bfloat16 sm[];
    uint32_t sbase = smem_u32(sm);

    int tid = threadIdx.x, lane = tid & 31, wid = tid >> 5;
    int wm = wid >> 1, wn = wid & 1;
    int m0 = blockIdx.y * 128, n0 = blockIdx.x * 128;

    const __nv_bfloat16* srcs[4] = {
        Ah + blockIdx.z * sA + (size_t)m0 * K,
        Al + blockIdx.z * sA + (size_t)m0 * K,
        Bh + blockIdx.z * sB + (size_t)n0 * K,
        Bl + blockIdx.z * sB + (size_t)n0 * K };
    C += blockIdx.z * sC;

    int g = lane >> 2, tg = lane & 3;
    const int nch = K >> 6;

    float acc[2][8][4];
#pragma unroll
    for (int a = 0; a < 2; a++)
#pragma unroll
        for (int b = 0; b < 8; b++)
#pragma unroll
            for (int c = 0; c < 4; c++) acc[a][b][c] = 0.f;

    auto load_stage = [&](int st, int c) {
#pragma unroll
        for (int t = 0; t < 4; t++) {
#pragma unroll
            for (int s = 0; s < 4; s++) {
                int i = tid + s * 256;
                int row = i >> 3, ch = (i & 7) * 8;
                const void* gp = srcs[t] + (size_t)row * K + c * BKC + ch;
                uint32_t dp = sbase + (uint32_t)(st * STAGE_ELE + t * TEN_ELE + row * STRD + ch) * 2;
                asm volatile("cp.async.cg.shared.global [%0], [%1], 16;" :: "r"(dp), "l"(gp));
            }
        }
        asm volatile("cp.async.commit_group;");
    };

    load_stage(0, 0);
    if (nch > 1) load_stage(1, 1);

    for (int c = 0; c < nch; c++) {
        if (c + 1 < nch) {
            asm volatile("cp.async.wait_group 1;");
        } else {
            asm volatile("cp.async.wait_group 0;");
        }
        __syncthreads();

        if (c + 2 < nch) load_stage((c + 2) % NSTAGE, c + 2);

        const __nv_bfloat16* sAh = sm + (size_t)(c % NSTAGE) * STAGE_ELE;
        const __nv_bfloat16* sAl = sAh + TEN_ELE;
        const __nv_bfloat16* sBh = sAh + 2 * TEN_ELE;
        const __nv_bfloat16* sBl = sAh + 3 * TEN_ELE;

#pragma unroll
        for (int ks = 0; ks < 4; ks++) {
            int k0 = ks * 16 + tg * 2;
            unsigned ah[2][4], al[2][4];
#pragma unroll
            for (int mt = 0; mt < 2; mt++) {
                int rb = wm * 32 + mt * 16 + g;
                ah[mt][0] = *(const unsigned*)(sAh + rb * STRD + k0);
                ah[mt][1] = *(const unsigned*)(sAh + (rb + 8) * STRD + k0);
                ah[mt][2] = *(const unsigned*)(sAh + rb * STRD + k0 + 8);
                ah[mt][3] = *(const unsigned*)(sAh + (rb + 8) * STRD + k0 + 8);
                al[mt][0] = *(const unsigned*)(sAl + rb * STRD + k0);
                al[mt][1] = *(const unsigned*)(sAl + (rb + 8) * STRD + k0);
                al[mt][2] = *(const unsigned*)(sAl + rb * STRD + k0 + 8);
                al[mt][3] = *(const unsigned*)(sAl + (rb + 8) * STRD + k0 + 8);
            }
#pragma unroll
            for (int nt = 0; nt < 8; nt++) {
                int cb = wn * 64 + nt * 8 + g;
                unsigned bh[2], bl[2];
                bh[0] = *(const unsigned*)(sBh + cb * STRD + k0);
                bh[1] = *(const unsigned*)(sBh + cb * STRD + k0 + 8);
                bl[0] = *(const unsigned*)(sBl + cb * STRD + k0);
                bl[1] = *(const unsigned*)(sBl + cb * STRD + k0 + 8);
                mma16816(acc[0][nt], ah[0], bh);
                mma16816(acc[1][nt], ah[1], bh);
                mma16816(acc[0][nt], ah[0], bl);
                mma16816(acc[1][nt], ah[1], bl);
                mma16816(acc[0][nt], al[0], bh);
                mma16816(acc[1][nt], al[1], bh);
            }
        }
        __syncthreads();
    }

#pragma unroll
    for (int mt = 0; mt < 2; mt++) {
        int row0 = m0 + wm * 32 + mt * 16 + g;
#pragma unroll
        for (int nt = 0; nt < 8; nt++) {
            int col = n0 + wn * 64 + nt * 8 + tg * 2;
            float2 v0, v1;
            v0.x = acc[mt][nt][0]; v0.y = acc[mt][nt][1];
            v1.x = acc[mt][nt][2]; v1.y = acc[mt][nt][3];
            if (BIAS) {
                float2 bv = *(const float2*)(bias + col);
                v0.x += bv.x; v0.y += bv.y;
                v1.x += bv.x; v1.y += bv.y;
            }
            *(float2*)(C + (size_t)row0 * 1024 + col) = v0;
            *(float2*)(C + (size_t)(row0 + 8) * 1024 + col) = v1;
        }
    }
}

// ================= K4: T partials — grid (4 echunks, 64 bn), conflict-free ========
__global__ void __launch_bounds__(256) k_Tp(const float* __restrict__ Wv) {
    __shared__ float sp[32 * 68];
    __shared__ float sw[64 * 64];
    int ec = blockIdx.x;
    int bn = blockIdx.y;
    int b = bn >> 4, n = bn & 15;
    int tid = threadIdx.x;
    int m = tid >> 3;
    int p = tid & 7;

    const float* P = g_P + ((size_t)b * 512 + n * 32) * EMBED + ec * 256;

    float acc[8];
#pragma unroll
    for (int c = 0; c < 8; c++) acc[c] = 0.f;

    for (int e0 = 0; e0 < 256; e0 += 64) {
        __syncthreads();
#pragma unroll
        for (int s = 0; s < 2; s++) {
            int f4 = tid + s * 256;
            int row = f4 >> 4, c4 = (f4 & 15) * 4;
            *(float4*)&sp[row * 68 + c4] = *(const float4*)(P + (size_t)row * EMBED + e0 + c4);
        }
#pragma unroll
        for (int s = 0; s < 4; s++) {
            int f4 = tid + s * 256;
            int row = f4 >> 4, c4 = (f4 & 15) * 4;
            *(float4*)&sw[row * 64 + c4] =
                *(const float4*)(Wv + (size_t)(ec * 256 + e0 + row) * (HEADS * HDIM) + n * 64 + c4);
        }
        __syncthreads();

#pragma unroll 4
        for (int e = 0; e < 64; e++) {
            float pv = sp[m * 68 + e];
            float4 w0 = *(const float4*)&sw[e * 64 + 4 * p];
            float4 w1 = *(const float4*)&sw[e * 64 + 32 + 4 * p];
            acc[0] += pv * w0.x; acc[1] += pv * w0.y;
            acc[2] += pv * w0.z; acc[3] += pv * w0.w;
            acc[4] += pv * w1.x; acc[5] += pv * w1.y;
            acc[6] += pv * w1.z; acc[7] += pv * w1.w;
        }
    }

    float* Tp = g_Tpart + (((size_t)ec * 64 + bn) * 32 + m) * 64;
    float4 o0, o1;
    o0.x = acc[0]; o0.y = acc[1]; o0.z = acc[2]; o0.w = acc[3];
    o1.x = acc[4]; o1.y = acc[5]; o1.z = acc[6]; o1.w = acc[7];
    *(float4*)(Tp + 4 * p) = o0;
    *(float4*)(Tp + 32 + 4 * p) = o1;
}

// ================= K5: U (sums T partials) + transpose/bf16 split -> UT ===========
#define KU_SMEM ((32 * 68 + 16 * 256 + 32 * 264) * 4)
__global__ void __launch_bounds__(256) k_U(const float* __restrict__ Wp) {
    extern __shared__ float us[];
    float* sT = us;
    float* sW = us + 32 * 68;
    float* sO = us + 32 * 68 + 16 * 256;

    int bn = blockIdx.y;
    int b = bn >> 4, n = bn & 15;
    int c0 = blockIdx.x * 256;
    int tid = threadIdx.x;
    int m = tid >> 3;
    int p = tid & 7;
    int dq4 = 4 * p;

#pragma unroll
    for (int s = 0; s < 2; s++) {
        int f4 = tid + s * 256;
        int row = f4 >> 4, c4 = (f4 & 15) * 4;
        size_t off = ((size_t)bn * 32 + row) * 64 + c4;
        float4 a0 = *(const float4*)(g_Tpart + off);
        float4 a1 = *(const float4*)(g_Tpart + (size_t)1 * 64 * 32 * 64 + off);
        float4 a2 = *(const float4*)(g_Tpart + (size_t)2 * 64 * 32 * 64 + off);
        float4 a3 = *(const float4*)(g_Tpart + (size_t)3 * 64 * 32 * 64 + off);
        float4 o;
        o.x = (a0.x + a1.x) + (a2.x + a3.x);
        o.y = (a0.y + a1.y) + (a2.y + a3.y);
        o.z = (a0.z + a1.z) + (a2.z + a3.z);
        o.w = (a0.w + a1.w) + (a2.w + a3.w);
        *(float4*)&sT[row * 68 + c4] = o;
    }

    float acc[32];
#pragma unroll
    for (int c = 0; c < 32; c++) acc[c] = 0.f;

    for (int dt = 0; dt < 4; dt++) {
        __syncthreads();
#pragma unroll
        for (int s = 0; s < 4; s++) {
            int f4 = tid + s * 256;
            int row = f4 >> 6, c4 = (f4 & 63) * 4;
            *(float4*)&sW[row * 256 + c4] =
                *(const float4*)(Wp + (size_t)(n * 64 + dt * 16 + row) * OUTD + c0 + c4);
        }
        __syncthreads();

#pragma unroll
        for (int d = 0; d < 16; d++) {
            float t = sT[m * 68 + dt * 16 + d];
#pragma unroll
            for (int k = 0; k < 8; k++) {
                float4 w = *(const float4*)&sW[d * 256 + k * 32 + dq4];
                acc[k * 4 + 0] += t * w.x;
                acc[k * 4 + 1] += t * w.y;
                acc[k * 4 + 2] += t * w.z;
                acc[k * 4 + 3] += t * w.w;
            }
        }
    }

#pragma unroll
    for (int k = 0; k < 8; k++) {
        float4 o;
        o.x = acc[k * 4 + 0]; o.y = acc[k * 4 + 1];
        o.z = acc[k * 4 + 2]; o.w = acc[k * 4 + 3];
        *(float4*)&sO[m * 264 + k * 32 + dq4] = o;
    }
    __syncthreads();

    {
        int o = c0 + tid;
        size_t rowbase = (((size_t)b * 1024) + o) * 512 + n * 32;
        unsigned hh[16], ll[16];
#pragma unroll
        for (int mm = 0; mm < 16; mm++) {
            float x0 = sO[(2 * mm) * 264 + tid];
            float x1 = sO[(2 * mm + 1) * 264 + tid];
            hh[mm] = pack_hi(x0, x1);
            ll[mm] = pack_lo(x0, x1);
        }
#pragma unroll
        for (int q = 0; q < 4; q++) {
            *(uint4*)(g_UTh + rowbase + q * 8) = *(uint4*)&hh[q * 4];
            *(uint4*)(g_UTl + rowbase + q * 8) = *(uint4*)&ll[q * 4];
        }
    }
}

// ================= K6: Phi~ (bf16 hi/lo, [i][nm]) =================
__global__ void __launch_bounds__(256) k_phiq() {
    __shared__ float syn[MCH];
    __shared__ float sS[16][MCH];
    int b = blockIdx.y;
    int tid = threadIdx.x;
    int n = tid & 15;
    int ir = tid >> 4;
    int i = blockIdx.x * 16 + ir;

    CHEB_LOCAL(syn, (float*)0, tid);
    for (int t = tid; t < 16 * MCH; t += 256) {
        int hn = t >> 5, m = t & 31;
        int bn = b * 16 + hn;
        float s = g_Spart[(0 * 64 + bn) * MCH + m] + g_Spart[(1 * 64 + bn) * MCH + m]
                + g_Spart[(2 * 64 + bn) * MCH + m] + g_Spart[(3 * 64 + bn) * MCH + m];
        sS[hn][m] = s;
    }
    __syncthreads();

    float sq = g_SQ[((b * 16 + n) << 10) + i];
    float phi[MCH];
    float den = 0.f;
#pragma unroll
    for (int m = 0; m < MCH; m++) {
        float u = __expf(2.f * (sq + syn[m]));
        float t = (u - 1.f) * frcp(u + 1.f);
        float p = __expf(t);
        phi[m] = p;
        den += p * sS[n][m];
    }
    float inv = frcp(den);

    size_t base = ((((size_t)b << 10) + i) * 512) + n * 32;
#pragma unroll
    for (int q8 = 0; q8 < 4; q8++) {
        unsigned hh[4], ll[4];
#pragma unroll
        for (int p2 = 0; p2 < 4; p2++) {
            float x0 = phi[q8 * 8 + p2 * 2]     * inv;
            float x1 = phi[q8 * 8 + p2 * 2 + 1] * inv;
            hh[p2] = pack_hi(x0, x1);
            ll[p2] = pack_lo(x0, x1);
        }
        *(uint4*)(g_Phih + base + q8 * 8) = *(uint4*)hh;
        *(uint4*)(g_Phil + base + q8 * 8) = *(uint4*)ll;
    }
}

// ================= K7: layernorm =================
__global__ void __launch_bounds__(256) k_ln(float* __restrict__ y,
                                            const float* __restrict__ gamma,
                                            const float* __restrict__ beta) {
    int row = blockIdx.x, tid = threadIdx.x;
    float4* yp = (float4*)(y + (size_t)row * 1024);
    float4 v = yp[tid];
    float s  = v.x + v.y + v.z + v.w;
    float ss = v.x * v.x + v.y * v.y + v.z * v.z + v.w * v.w;

    __shared__ float red[16];
    int lane = tid & 31, wid = tid >> 5;
#pragma unroll
    for (int o = 16; o; o >>= 1) {
        s  += __shfl_xor_sync(0xffffffffu, s,  o);
        ss += __shfl_xor_sync(0xffffffffu, ss, o);
    }
    if (lane == 0) { red[wid] = s; red[wid + 8] = ss; }
    __syncthreads();
    if (tid == 0) {
        float S = 0.f, SS = 0.f;
        for (int w = 0; w < 8; w++) { S += red[w]; SS += red[w + 8]; }
        red[0] = S; red[1] = SS;
    }
    __syncthreads();
    float mean = red[0] * (1.0f / 1024.0f);
    float var  = red[1] * (1.0f / 1024.0f) - mean * mean;
    float rr = rsqrtf(var + 1e-6f);

    float4 g  = ((const float4*)gamma)[tid];
    float4 bb = ((const float4*)beta)[tid];
    float4 o;
    o.x = (v.x - mean) * rr * g.x + bb.x;
    o.y = (v.y - mean) * rr * g.y + bb.y;
    o.z = (v.z - mean) * rr * g.z + bb.z;
    o.w = (v.w - mean) * rr * g.w + bb.w;
    yp[tid] = o;
}

// ================= launcher =================
extern "C" void kernel_launch(void* const* d_in, const int* in_sizes, int n_in,
                              void* d_out, int out_size) {
    (void)n_in; (void)out_size;
    const float* k_in  = (const float*)d_in[0];
    const float* q_in  = (const float*)d_in[1];
    const float* v_in  = (const float*)d_in[2];
    const float* Wq    = (const float*)d_in[3];
    const float* bq    = (const float*)d_in[4];
    const float* Wk    = (const float*)d_in[5];
    const float* Wv    = (const float*)d_in[6];
    const float* Wp    = (const float*)d_in[7];
    const float* bp    = (const float*)d_in[8];
    const float* aw    = (const float*)d_in[9];
    const float* gamma = (const float*)d_in[10];
    const float* beta  = (const float*)d_in[11];
    float* out = (float*)d_out;

    int B = in_sizes[0] / (LSEQ * EMBED);   // 4
    int M = B * LSEQ;                        // 4096

    float* p_P = nullptr;
    __nv_bfloat16 *p_Psih, *p_Psil, *p_VTh, *p_VTl, *p_Phih, *p_Phil, *p_UTh, *p_UTl;
    cudaGetSymbolAddress((void**)&p_P,    g_P);
    cudaGetSymbolAddress((void**)&p_Psih, g_Psih);
    cudaGetSymbolAddress((void**)&p_Psil, g_Psil);
    cudaGetSymbolAddress((void**)&p_VTh,  g_VTh);
    cudaGetSymbolAddress((void**)&p_VTl,  g_VTl);
    cudaGetSymbolAddress((void**)&p_Phih, g_Phih);
    cudaGetSymbolAddress((void**)&p_Phil, g_Phil);
    cudaGetSymbolAddress((void**)&p_UTh,  g_UTh);
    cudaGetSymbolAddress((void**)&p_UTl,  g_UTl);

    cudaFuncSetAttribute(k_sqk, cudaFuncAttributeMaxDynamicSharedMemorySize, SQK_SMEM);
    cudaFuncSetAttribute(k_U,   cudaFuncAttributeMaxDynamicSharedMemorySize, KU_SMEM);
    cudaFuncSetAttribute(k_gemm_mma<false>, cudaFuncAttributeMaxDynamicSharedMemorySize, MMA_SMEM);
    cudaFuncSetAttribute(k_gemm_mma<true>,  cudaFuncAttributeMaxDynamicSharedMemorySize, MMA_SMEM);

    k_weff<<<128, 256>>>(Wq, Wk, bq, aw);                               // 0
    k_prepv<<<dim3(32, 16, B), 256>>>(v_in, 0);                         // 1
    k_prepv<<<dim3(32, 16, B), 256>>>(v_in, 1);                         // 2
    k_sqk<<<dim3(M / 32, 2), 256, SQK_SMEM>>>(q_in, k_in);              // 3 <- profiled
    k_psimat<<<dim3(LSEQ / 256, B * HEADS), 256>>>();                   // 4
    // P[b] (512 x 1024) = Psi_b @ v_b   (HMMA, K = 1024)
    k_gemm_mma<false><<<dim3(8, 4, B), 256, MMA_SMEM>>>(
        p_Psih, p_Psil, p_VTh, p_VTl, nullptr, p_P,
        1024, (size_t)512 * 1024, (size_t)1024 * 1024, (size_t)512 * 1024);
    k_phiq<<<dim3(LSEQ / 16, B), 256>>>();
    k_Tp<<<dim3(4, B * HEADS), 256>>>(Wv);
    k_U<<<dim3(4, B * HEADS), 256, KU_SMEM>>>(Wp);
    // out[b] (1024 x 1024) = Phi_b @ U_b + bp   (HMMA, K = 512)
    k_gemm_mma<true><<<dim3(8, 8, B), 256, MMA_SMEM>>>(
        p_Phih, p_Phil, p_UTh, p_UTl, bp, out,
        512, (size_t)1024 * 512, (size_t)1024 * 512, (size_t)1024 * 1024);
    k_ln<<<M, 256>>>(out, gamma, beta);
}

// round 16
// speedup vs baseline: 1.0629x; 1.0134x over previous
#include <cuda_runtime.h>
#include <cuda_bf16.h>
#include <cstdint>

#define EMBED 1024
#define HEADS 16
#define HDIM  64
#define LSEQ  1024
#define MAXB  4
#define MCH   32
#define OUTD  1024
#define PIF   3.14159265358979f

typedef unsigned long long u64;

// ================= helpers =================
__device__ __forceinline__ float frcp(float x) {
    float r; asm("rcp.approx.f32 %0, %1;" : "=f"(r) : "f"(x)); return r;
}
__device__ __forceinline__ u64 fma2(u64 a, u64 b, u64 c) {
    u64 d;
    asm("fma.rn.f32x2 %0, %1, %2, %3;" : "=l"(d) : "l"(a), "l"(b), "l"(c));
    return d;
}
__device__ __forceinline__ uint32_t smem_u32(const void* p) {
    uint32_t a;
    asm("{ .reg .u64 t; cvta.to.shared.u64 t, %1; cvt.u32.u64 %0, t; }" : "=r"(a) : "l"(p));
    return a;
}
__device__ __forceinline__ void mma16816(float* c, const unsigned* a, const unsigned* b) {
    asm volatile(
        "mma.sync.aligned.m16n8k16.row.col.f32.bf16.bf16.f32 "
        "{%0,%1,%2,%3}, {%4,%5,%6,%7}, {%8,%9}, {%0,%1,%2,%3};"
        : "+f"(c[0]), "+f"(c[1]), "+f"(c[2]), "+f"(c[3])
        : "r"(a[0]), "r"(a[1]), "r"(a[2]), "r"(a[3]), "r"(b[0]), "r"(b[1]));
}
__device__ __forceinline__ void ldsm_x4(unsigned* r, uint32_t addr) {
    asm volatile("ldmatrix.sync.aligned.m8n8.x4.shared.b16 {%0,%1,%2,%3}, [%4];"
        : "=r"(r[0]), "=r"(r[1]), "=r"(r[2]), "=r"(r[3]) : "r"(addr));
}
__device__ __forceinline__ unsigned pack_hi(float x0, float x1) {
    __nv_bfloat162 h;
    h.x = __float2bfloat16(x0);
    h.y = __float2bfloat16(x1);
    return *(unsigned*)&h;
}
__device__ __forceinline__ unsigned pack_lo(float x0, float x1) {
    __nv_bfloat16 h0 = __float2bfloat16(x0);
    __nv_bfloat16 h1 = __float2bfloat16(x1);
    __nv_bfloat162 l;
    l.x = __float2bfloat16(x0 - __bfloat162float(h0));
    l.y = __float2bfloat16(x1 - __bfloat162float(h1));
    return *(unsigned*)&l;
}

// ================= scratch =================
__device__ float g_WqE[EMBED * HEADS];
__device__ float g_WkE[EMBED * HEADS];
__device__ float g_bqE[HEADS];
__device__ float g_SQ[MAXB * HEADS * LSEQ];
__device__ float g_SK[MAXB * HEADS * LSEQ];
__device__ unsigned g_skmax_bits;
__device__ float g_Spart[4 * MAXB * HEADS * MCH];
__device__ float g_P[(size_t)MAXB * 512 * EMBED];
__device__ float g_Tpart[4 * MAXB * HEADS * MCH * HDIM];   // [ec][bn][m][d]

__device__ __align__(16) __nv_bfloat16 g_Psih[(size_t)MAXB * 512 * LSEQ];
__device__ __align__(16) __nv_bfloat16 g_Psil[(size_t)MAXB * 512 * LSEQ];
__device__ __align__(16) __nv_bfloat16 g_VTh[(size_t)MAXB * 1024 * 1024];
__device__ __align__(16) __nv_bfloat16 g_VTl[(size_t)MAXB * 1024 * 1024];
__device__ __align__(16) __nv_bfloat16 g_Phih[(size_t)MAXB * LSEQ * 512];
__device__ __align__(16) __nv_bfloat16 g_Phil[(size_t)MAXB * LSEQ * 512];
__device__ __align__(16) __nv_bfloat16 g_UTh[(size_t)MAXB * 1024 * 512];
__device__ __align__(16) __nv_bfloat16 g_UTl[(size_t)MAXB * 1024 * 512];

// ================= K0a: effective weights =================
__global__ void k_weff(const float* __restrict__ Wq, const float* __restrict__ Wk,
                       const float* __restrict__ bq, const float* __restrict__ aw) {
    int t = blockIdx.x * blockDim.x + threadIdx.x;
    if (t == 0) g_skmax_bits = 0u;
    int side = t >> 14;
    int u = t & 16383;
    int e = u >> 4, n = u & 15;
    const float* W = side ? Wk : Wq;
    const float* w = aw + side * HDIM;
    float s = 0.f;
#pragma unroll 8
    for (int d = 0; d < HDIM; d++)
        s += W[(size_t)e * (HEADS * HDIM) + n * HDIM + d] * w[d];
    if (side) g_WkE[e * 16 + n] = s;
    else      g_WqE[e * 16 + n] = s;
    if (!side && e == 0) {
        float sb = 0.f;
#pragma unroll 8
        for (int d = 0; d < HDIM; d++) sb += bq[n * HDIM + d] * w[d];
        g_bqE[n] = sb;
    }
}

// ================= K0b: V transpose + bf16 split (half grid per launch) ===========
__global__ void __launch_bounds__(256) k_prepv(const float* __restrict__ vin, int half) {
    __shared__ float tsm[32][33];
    int cx = blockIdx.x, cy = blockIdx.y + half * 16, b = blockIdx.z;
    const float* in = vin + (size_t)b * 1024 * 1024;
    __nv_bfloat16* oh = g_VTh + (size_t)b * 1024 * 1024;
    __nv_bfloat16* ol = g_VTl + (size_t)b * 1024 * 1024;
    int r0 = cy * 32, c0 = cx * 32;
    int tx = threadIdx.x & 31, ty = threadIdx.x >> 5;
#pragma unroll
    for (int s = 0; s < 4; s++) {
        int r = ty + s * 8;
        tsm[r][tx] = in[(size_t)(r0 + r) * 1024 + c0 + tx];
    }
    __syncthreads();
#pragma unroll
    for (int s = 0; s < 4; s++) {
        int c = ty + s * 8;
        float x = tsm[tx][c];
        __nv_bfloat16 h = __float2bfloat16(x);
        size_t o = (size_t)(c0 + c) * 1024 + r0 + tx;
        oh[o] = h;
        ol[o] = __float2bfloat16(x - __bfloat162float(h));
    }
}

// ================= K1: sq/sk =======================================================
#define PADF 1028
#define SQK_SMEM (16 * PADF * 4)
__global__ void __launch_bounds__(256) k_sqk(const float* __restrict__ qin,
                                             const float* __restrict__ kin) {
    extern __shared__ float sWEt[];
    __shared__ float sred[8];
    int side = blockIdx.y;
    const float* WE = side ? g_WkE : g_WqE;
    int tid = threadIdx.x;

    for (int idx = tid; idx < EMBED * HEADS; idx += 256) {
        int e = idx >> 4, n = idx & 15;
        sWEt[n * PADF + e] = WE[idx];
    }
    __syncthreads();

    int rl = tid >> 3;
    int p  = tid & 7;
    int row = blockIdx.x * 32 + rl;
    const float* xr = (side ? kin : qin) + (size_t)row * EMBED;

    u64 acc[16];
#pragma unroll
    for (int n = 0; n < 16; n++) acc[n] = 0ull;

#pragma unroll 4
    for (int i = 0; i < 32; i++) {
        int e = (i * 8 + p) * 4;
        float4 xv = *(const float4*)(xr + e);
        u64 xlo, xhi;
        asm("mov.b64 %0, {%1, %2};" : "=l"(xlo) : "f"(xv.x), "f"(xv.y));
        asm("mov.b64 %0, {%1, %2};" : "=l"(xhi) : "f"(xv.z), "f"(xv.w));
#pragma unroll
        for (int n = 0; n < 16; n++) {
            float4 wv = *(const float4*)&sWEt[n * PADF + e];
            u64 wlo, whi;
            asm("mov.b64 %0, {%1, %2};" : "=l"(wlo) : "f"(wv.x), "f"(wv.y));
            asm("mov.b64 %0, {%1, %2};" : "=l"(whi) : "f"(wv.z), "f"(wv.w));
            acc[n] = fma2(xlo, wlo, acc[n]);
            acc[n] = fma2(xhi, whi, acc[n]);
        }
    }

    float s[16];
#pragma unroll
    for (int n = 0; n < 16; n++) {
        float lo, hi;
        asm("mov.b64 {%0, %1}, %2;" : "=f"(lo), "=f"(hi) : "l"(acc[n]));
        s[n] = lo + hi;
    }
#pragma unroll
    for (int msk = 1; msk < 8; msk <<= 1)
#pragma unroll
        for (int n = 0; n < 16; n++)
            s[n] += __shfl_xor_sync(0xffffffffu, s[n], msk);

    int n0 = p * 2;
    float v0 = s[n0], v1 = s[n0 + 1];
    if (!side) { v0 += g_bqE[n0]; v1 += g_bqE[n0 + 1]; }
    int b = row >> 10, ii = row & 1023;
    float* dst = side ? g_SK : g_SQ;
    dst[((b * 16 + n0) << 10) + ii]     = v0;
    dst[((b * 16 + n0 + 1) << 10) + ii] = v1;

    if (side) {
        float a = fmaxf(fabsf(v0), fabsf(v1));
        int lane = tid & 31, wid = tid >> 5;
#pragma unroll
        for (int o = 16; o; o >>= 1) a = fmaxf(a, __shfl_xor_sync(0xffffffffu, a, o));
        if (lane == 0) sred[wid] = a;
        __syncthreads();
        if (tid == 0) {
            float mx = 0.f;
#pragma unroll
            for (int w2 = 0; w2 < 8; w2++) mx = fmaxf(mx, sred[w2]);
            atomicMax(&g_skmax_bits, __float_as_uint(mx));
        }
    }
}

// ---- inline Chebyshev nodes ----
#define CHEB_LOCAL(yn, wb, tid) do { \
    if ((tid) < MCH) { \
        float smax = __uint_as_float(g_skmax_bits); \
        float Y = smax * 1.0005f + 1e-6f; \
        float th = (2.f * (tid) + 1.f) * (PIF / 64.f); \
        (yn)[tid] = Y * cosf(th); \
        if (wb) ((float*)(wb))[tid] = (((tid) & 1) ? -sinf(th) : sinf(th)); \
    } \
} while (0)

// ================= K2: Psi + S partials =================
__global__ void __launch_bounds__(256) k_psimat() {
    __shared__ float sp[256][33];
    __shared__ float colsum[8][32];
    __shared__ float yn[MCH], wb[MCH];
    int bn = blockIdx.y;
    int b = bn >> 4, n = bn & 15;
    int jc = blockIdx.x;
    int j0 = jc * 256;
    int tid = threadIdx.x;
    CHEB_LOCAL(yn, wb, tid);
    __syncthreads();

    {
        float y = g_SK[(bn << 10) + j0 + tid];
        float t[MCH];
        float den = 0.f;
#pragma unroll
        for (int m = 0; m < MCH; m++) {
            float d = y - yn[m];
            d = (fabsf(d) < 1e-12f) ? 1e-12f : d;
            t[m] = wb[m] * frcp(d);
            den += t[m];
        }
        float ri = frcp(den);
#pragma unroll
        for (int m = 0; m < MCH; m++) sp[tid][m] = t[m] * ri;
    }
    __syncthreads();

    {
        int m = tid & 31, seg = tid >> 5;
        float s = 0.f;
#pragma unroll 8
        for (int r = 0; r < 32; r++) s += sp[seg * 32 + r][m];
        colsum[seg][m] = s;
    }
    __syncthreads();
    if (tid < 32) {
        float t = 0.f;
#pragma unroll
        for (int s8 = 0; s8 < 8; s8++) t += colsum[s8][tid];
        g_Spart[(jc * 64 + bn) * MCH + tid] = t;
    }

    int r  = tid >> 3;
    int cg = (tid & 7) * 32;
    size_t base = (((size_t)b * 512) + n * 32 + r) * LSEQ + j0 + cg;
#pragma unroll
    for (int q8 = 0; q8 < 4; q8++) {
        unsigned hh[4], ll[4];
#pragma unroll
        for (int p2 = 0; p2 < 4; p2++) {
            float x0 = sp[cg + q8 * 8 + p2 * 2][r];
            float x1 = sp[cg + q8 * 8 + p2 * 2 + 1][r];
            hh[p2] = pack_hi(x0, x1);
            ll[p2] = pack_lo(x0, x1);
        }
        *(uint4*)(g_Psih + base + q8 * 8) = *(uint4*)hh;
        *(uint4*)(g_Psil + base + q8 * 8) = *(uint4*)ll;
    }
}

// ================= HMMA bf16-split GEMM — 3-stage cp.async + ldmatrix =============
#define BKC 64
#define STRD 72
#define STRDB (STRD * 2)
#define TEN_ELE (128 * STRD)
#define STAGE_ELE (4 * TEN_ELE)
#define NSTAGE 3
#define MMA_SMEM (NSTAGE * STAGE_ELE * 2)

template <bool BIAS>
__global__ void __launch_bounds__(256) k_gemm_mma(
    const __nv_bfloat16* __restrict__ Ah, const __nv_bfloat16* __restrict__ Al,
    const __nv_bfloat16* __restrict__ Bh, const __nv_bfloat16* __restrict__ Bl,
    const float* __restrict__ bias, float* __restrict__ C,
    int K, size_t sA, size_t sB, size_t sC)
{
    extern __shared__ __nv_bfloat16 sm[];
    uint32_t sbase = smem_u32(sm);

    int tid = threadIdx.x, lane = tid & 31, wid = tid >> 5;
    int wm = wid >> 1, wn = wid & 1;
    int m0 = blockIdx.y * 128, n0 = blockIdx.x * 128;

    const __nv_bfloat16* srcs[4] = {
        Ah + blockIdx.z * sA + (size_t)m0 * K,
        Al + blockIdx.z * sA + (size_t)m0 * K,
        Bh + blockIdx.z * sB + (size_t)n0 * K,
        Bl + blockIdx.z * sB + (size_t)n0 * K };
    C += blockIdx.z * sC;

    int g = lane >> 2, tg = lane & 3;
    const int nch = K >> 6;

    // ldmatrix lane addressing (verified in R9)
    int lam = lane & 15;
    int lakB = (lane & 16) ? 16 : 0;
    int lbn = (lane & 7) + ((lane & 16) ? 8 : 0);
    int lbkB = (lane & 8) ? 16 : 0;

    float acc[2][8][4];
#pragma unroll
    for (int a = 0; a < 2; a++)
#pragma unroll
        for (int b = 0; b < 8; b++)
#pragma unroll
            for (int c = 0; c < 4; c++) acc[a][b][c] = 0.f;

    auto load_stage = [&](int st, int c) {
#pragma unroll
        for (int t = 0; t < 4; t++) {
#pragma unroll
            for (int s = 0; s < 4; s++) {
                int i = tid + s * 256;
                int row = i >> 3, ch = (i & 7) * 8;
                const void* gp = srcs[t] + (size_t)row * K + c * BKC + ch;
                uint32_t dp = sbase + (uint32_t)(st * STAGE_ELE + t * TEN_ELE + row * STRD + ch) * 2;
                asm volatile("cp.async.cg.shared.global [%0], [%1], 16;" :: "r"(dp), "l"(gp));
            }
        }
        asm volatile("cp.async.commit_group;");
    };

    load_stage(0, 0);
    if (nch > 1) load_stage(1, 1);

    for (int c = 0; c < nch; c++) {
        if (c + 1 < nch) {
            asm volatile("cp.async.wait_group 1;");
        } else {
            asm volatile("cp.async.wait_group 0;");
        }
        __syncthreads();

        if (c + 2 < nch) load_stage((c + 2) % NSTAGE, c + 2);

        uint32_t sb = sbase + (uint32_t)((c % NSTAGE) * STAGE_ELE) * 2;
        uint32_t aAh = sb + (uint32_t)(wm * 32 + lam) * STRDB + lakB;
        uint32_t aAl = aAh + TEN_ELE * 2;
        uint32_t aBh = sb + 2u * TEN_ELE * 2 + (uint32_t)(wn * 64 + lbn) * STRDB + lbkB;
        uint32_t aBl = aBh + TEN_ELE * 2;

#pragma unroll
        for (int ks = 0; ks < 4; ks++) {
            unsigned ah0[4], ah1[4], al0[4], al1[4];
            ldsm_x4(ah0, aAh + ks * 32);
            ldsm_x4(ah1, aAh + 16 * STRDB + ks * 32);
            ldsm_x4(al0, aAl + ks * 32);
            ldsm_x4(al1, aAl + 16 * STRDB + ks * 32);
#pragma unroll
            for (int ntp = 0; ntp < 4; ntp++) {
                unsigned bh[4], bl[4];
                ldsm_x4(bh, aBh + ntp * 16 * STRDB + ks * 32);
                ldsm_x4(bl, aBl + ntp * 16 * STRDB + ks * 32);
                int nt = 2 * ntp;
                mma16816(acc[0][nt],     ah0, bh);
                mma16816(acc[0][nt + 1], ah0, bh + 2);
                mma16816(acc[1][nt],     ah1, bh);
                mma16816(acc[1][nt + 1], ah1, bh + 2);
                mma16816(acc[0][nt],     ah0, bl);
                mma16816(acc[0][nt + 1], ah0, bl + 2);
                mma16816(acc[1][nt],     ah1, bl);
                mma16816(acc[1][nt + 1], ah1, bl + 2);
                mma16816(acc[0][nt],     al0, bh);
                mma16816(acc[0][nt + 1], al0, bh + 2);
                mma16816(acc[1][nt],     al1, bh);
                mma16816(acc[1][nt + 1], al1, bh + 2);
            }
        }
        __syncthreads();
    }

#pragma unroll
    for (int mt = 0; mt < 2; mt++) {
        int row0 = m0 + wm * 32 + mt * 16 + g;
#pragma unroll
        for (int nt = 0; nt < 8; nt++) {
            int col = n0 + wn * 64 + nt * 8 + tg * 2;
            float2 v0, v1;
            v0.x = acc[mt][nt][0]; v0.y = acc[mt][nt][1];
            v1.x = acc[mt][nt][2]; v1.y = acc[mt][nt][3];
            if (BIAS) {
                float2 bv = *(const float2*)(bias + col);
                v0.x += bv.x; v0.y += bv.y;
                v1.x += bv.x; v1.y += bv.y;
            }
            *(float2*)(C + (size_t)row0 * 1024 + col) = v0;
            *(float2*)(C + (size_t)(row0 + 8) * 1024 + col) = v1;
        }
    }
}

// ================= K4: T partials — grid (4 echunks, 64 bn), conflict-free ========
__global__ void __launch_bounds__(256) k_Tp(const float* __restrict__ Wv) {
    __shared__ float sp[32 * 68];
    __shared__ float sw[64 * 64];
    int ec = blockIdx.x;
    int bn = blockIdx.y;
    int b = bn >> 4, n = bn & 15;
    int tid = threadIdx.x;
    int m = tid >> 3;
    int p = tid & 7;

    const float* P = g_P + ((size_t)b * 512 + n * 32) * EMBED + ec * 256;

    float acc[8];
#pragma unroll
    for (int c = 0; c < 8; c++) acc[c] = 0.f;

    for (int e0 = 0; e0 < 256; e0 += 64) {
        __syncthreads();
#pragma unroll
        for (int s = 0; s < 2; s++) {
            int f4 = tid + s * 256;
            int row = f4 >> 4, c4 = (f4 & 15) * 4;
            *(float4*)&sp[row * 68 + c4] = *(const float4*)(P + (size_t)row * EMBED + e0 + c4);
        }
#pragma unroll
        for (int s = 0; s < 4; s++) {
            int f4 = tid + s * 256;
            int row = f4 >> 4, c4 = (f4 & 15) * 4;
            *(float4*)&sw[row * 64 + c4] =
                *(const float4*)(Wv + (size_t)(ec * 256 + e0 + row) * (HEADS * HDIM) + n * 64 + c4);
        }
        __syncthreads();

#pragma unroll 4
        for (int e = 0; e < 64; e++) {
            float pv = sp[m * 68 + e];
            float4 w0 = *(const float4*)&sw[e * 64 + 4 * p];
            float4 w1 = *(const float4*)&sw[e * 64 + 32 + 4 * p];
            acc[0] += pv * w0.x; acc[1] += pv * w0.y;
            acc[2] += pv * w0.z; acc[3] += pv * w0.w;
            acc[4] += pv * w1.x; acc[5] += pv * w1.y;
            acc[6] += pv * w1.z; acc[7] += pv * w1.w;
        }
    }

    float* Tp = g_Tpart + (((size_t)ec * 64 + bn) * 32 + m) * 64;
    float4 o0, o1;
    o0.x = acc[0]; o0.y = acc[1]; o0.z = acc[2]; o0.w = acc[3];
    o1.x = acc[4]; o1.y = acc[5]; o1.z = acc[6]; o1.w = acc[7];
    *(float4*)(Tp + 4 * p) = o0;
    *(float4*)(Tp + 32 + 4 * p) = o1;
}

// ================= K5: U (sums T partials) + transpose/bf16 split -> UT ===========
#define KU_SMEM ((32 * 68 + 16 * 256 + 32 * 264) * 4)
__global__ void __launch_bounds__(256) k_U(const float* __restrict__ Wp) {
    extern __shared__ float us[];
    float* sT = us;
    float* sW = us + 32 * 68;
    float* sO = us + 32 * 68 + 16 * 256;

    int bn = blockIdx.y;
    int b = bn >> 4, n = bn & 15;
    int c0 = blockIdx.x * 256;
    int tid = threadIdx.x;
    int m = tid >> 3;
    int p = tid & 7;
    int dq4 = 4 * p;

#pragma unroll
    for (int s = 0; s < 2; s++) {
        int f4 = tid + s * 256;
        int row = f4 >> 4, c4 = (f4 & 15) * 4;
        size_t off = ((size_t)bn * 32 + row) * 64 + c4;
        float4 a0 = *(const float4*)(g_Tpart + off);
        float4 a1 = *(const float4*)(g_Tpart + (size_t)1 * 64 * 32 * 64 + off);
        float4 a2 = *(const float4*)(g_Tpart + (size_t)2 * 64 * 32 * 64 + off);
        float4 a3 = *(const float4*)(g_Tpart + (size_t)3 * 64 * 32 * 64 + off);
        float4 o;
        o.x = (a0.x + a1.x) + (a2.x + a3.x);
        o.y = (a0.y + a1.y) + (a2.y + a3.y);
        o.z = (a0.z + a1.z) + (a2.z + a3.z);
        o.w = (a0.w + a1.w) + (a2.w + a3.w);
        *(float4*)&sT[row * 68 + c4] = o;
    }

    float acc[32];
#pragma unroll
    for (int c = 0; c < 32; c++) acc[c] = 0.f;

    for (int dt = 0; dt < 4; dt++) {
        __syncthreads();
#pragma unroll
        for (int s = 0; s < 4; s++) {
            int f4 = tid + s * 256;
            int row = f4 >> 6, c4 = (f4 & 63) * 4;
            *(float4*)&sW[row * 256 + c4] =
                *(const float4*)(Wp + (size_t)(n * 64 + dt * 16 + row) * OUTD + c0 + c4);
        }
        __syncthreads();

#pragma unroll
        for (int d = 0; d < 16; d++) {
            float t = sT[m * 68 + dt * 16 + d];
#pragma unroll
            for (int k = 0; k < 8; k++) {
                float4 w = *(const float4*)&sW[d * 256 + k * 32 + dq4];
                acc[k * 4 + 0] += t * w.x;
                acc[k * 4 + 1] += t * w.y;
                acc[k * 4 + 2] += t * w.z;
                acc[k * 4 + 3] += t * w.w;
            }
        }
    }

#pragma unroll
    for (int k = 0; k < 8; k++) {
        float4 o;
        o.x = acc[k * 4 + 0]; o.y = acc[k * 4 + 1];
        o.z = acc[k * 4 + 2]; o.w = acc[k * 4 + 3];
        *(float4*)&sO[m * 264 + k * 32 + dq4] = o;
    }
    __syncthreads();

    {
        int o = c0 + tid;
        size_t rowbase = (((size_t)b * 1024) + o) * 512 + n * 32;
        unsigned hh[16], ll[16];
#pragma unroll
        for (int mm = 0; mm < 16; mm++) {
            float x0 = sO[(2 * mm) * 264 + tid];
            float x1 = sO[(2 * mm + 1) * 264 + tid];
            hh[mm] = pack_hi(x0, x1);
            ll[mm] = pack_lo(x0, x1);
        }
#pragma unroll
        for (int q = 0; q < 4; q++) {
            *(uint4*)(g_UTh + rowbase + q * 8) = *(uint4*)&hh[q * 4];
            *(uint4*)(g_UTl + rowbase + q * 8) = *(uint4*)&ll[q * 4];
        }
    }
}

// ================= K6: Phi~ (bf16 hi/lo, [i][nm]) =================
__global__ void __launch_bounds__(256) k_phiq() {
    __shared__ float syn[MCH];
    __shared__ float sS[16][MCH];
    int b = blockIdx.y;
    int tid = threadIdx.x;
    int n = tid & 15;
    int ir = tid >> 4;
    int i = blockIdx.x * 16 + ir;

    CHEB_LOCAL(syn, (float*)0, tid);
    for (int t = tid; t < 16 * MCH; t += 256) {
        int hn = t >> 5, m = t & 31;
        int bn = b * 16 + hn;
        float s = g_Spart[(0 * 64 + bn) * MCH + m] + g_Spart[(1 * 64 + bn) * MCH + m]
                + g_Spart[(2 * 64 + bn) * MCH + m] + g_Spart[(3 * 64 + bn) * MCH + m];
        sS[hn][m] = s;
    }
    __syncthreads();

    float sq = g_SQ[((b * 16 + n) << 10) + i];
    float phi[MCH];
    float den = 0.f;
#pragma unroll
    for (int m = 0; m < MCH; m++) {
        float u = __expf(2.f * (sq + syn[m]));
        float t = (u - 1.f) * frcp(u + 1.f);
        float p = __expf(t);
        phi[m] = p;
        den += p * sS[n][m];
    }
    float inv = frcp(den);

    size_t base = ((((size_t)b << 10) + i) * 512) + n * 32;
#pragma unroll
    for (int q8 = 0; q8 < 4; q8++) {
        unsigned hh[4], ll[4];
#pragma unroll
        for (int p2 = 0; p2 < 4; p2++) {
            float x0 = phi[q8 * 8 + p2 * 2]     * inv;
            float x1 = phi[q8 * 8 + p2 * 2 + 1] * inv;
            hh[p2] = pack_hi(x0, x1);
            ll[p2] = pack_lo(x0, x1);
        }
        *(uint4*)(g_Phih + base + q8 * 8) = *(uint4*)hh;
        *(uint4*)(g_Phil + base + q8 * 8) = *(uint4*)ll;
    }
}

// ================= K7: layernorm =================
__global__ void __launch_bounds__(256) k_ln(float* __restrict__ y,
                                            const float* __restrict__ gamma,
                                            const float* __restrict__ beta) {
    int row = blockIdx.x, tid = threadIdx.x;
    float4* yp = (float4*)(y + (size_t)row * 1024);
    float4 v = yp[tid];
    float s  = v.x + v.y + v.z + v.w;
    float ss = v.x * v.x + v.y * v.y + v.z * v.z + v.w * v.w;

    __shared__ float red[16];
    int lane = tid & 31, wid = tid >> 5;
#pragma unroll
    for (int o = 16; o; o >>= 1) {
        s  += __shfl_xor_sync(0xffffffffu, s,  o);
        ss += __shfl_xor_sync(0xffffffffu, ss, o);
    }
    if (lane == 0) { red[wid] = s; red[wid + 8] = ss; }
    __syncthreads();
    if (tid == 0) {
        float S = 0.f, SS = 0.f;
        for (int w = 0; w < 8; w++) { S += red[w]; SS += red[w + 8]; }
        red[0] = S; red[1] = SS;
    }
    __syncthreads();
    float mean = red[0] * (1.0f / 1024.0f);
    float var  = red[1] * (1.0f / 1024.0f) - mean * mean;
    float rr = rsqrtf(var + 1e-6f);

    float4 g  = ((const float4*)gamma)[tid];
    float4 bb = ((const float4*)beta)[tid];
    float4 o;
    o.x = (v.x - mean) * rr * g.x + bb.x;
    o.y = (v.y - mean) * rr * g.y + bb.y;
    o.z = (v.z - mean) * rr * g.z + bb.z;
    o.w = (v.w - mean) * rr * g.w + bb.w;
    yp[tid] = o;
}

// ================= launcher =================
extern "C" void kernel_launch(void* const* d_in, const int* in_sizes, int n_in,
                              void* d_out, int out_size) {
    (void)n_in; (void)out_size;
    const float* k_in  = (const float*)d_in[0];
    const float* q_in  = (const float*)d_in[1];
    const float* v_in  = (const float*)d_in[2];
    const float* Wq    = (const float*)d_in[3];
    const float* bq    = (const float*)d_in[4];
    const float* Wk    = (const float*)d_in[5];
    const float* Wv    = (const float*)d_in[6];
    const float* Wp    = (const float*)d_in[7];
    const float* bp    = (const float*)d_in[8];
    const float* aw    = (const float*)d_in[9];
    const float* gamma = (const float*)d_in[10];
    const float* beta  = (const float*)d_in[11];
    float* out = (float*)d_out;

    int B = in_sizes[0] / (LSEQ * EMBED);   // 4
    int M = B * LSEQ;                        // 4096

    float* p_P = nullptr;
    __nv_bfloat16 *p_Psih, *p_Psil, *p_VTh, *p_VTl, *p_Phih, *p_Phil, *p_UTh, *p_UTl;
    cudaGetSymbolAddress((void**)&p_P,    g_P);
    cudaGetSymbolAddress((void**)&p_Psih, g_Psih);
    cudaGetSymbolAddress((void**)&p_Psil, g_Psil);
    cudaGetSymbolAddress((void**)&p_VTh,  g_VTh);
    cudaGetSymbolAddress((void**)&p_VTl,  g_VTl);
    cudaGetSymbolAddress((void**)&p_Phih, g_Phih);
    cudaGetSymbolAddress((void**)&p_Phil, g_Phil);
    cudaGetSymbolAddress((void**)&p_UTh,  g_UTh);
    cudaGetSymbolAddress((void**)&p_UTl,  g_UTl);

    cudaFuncSetAttribute(k_sqk, cudaFuncAttributeMaxDynamicSharedMemorySize, SQK_SMEM);
    cudaFuncSetAttribute(k_U,   cudaFuncAttributeMaxDynamicSharedMemorySize, KU_SMEM);
    cudaFuncSetAttribute(k_gemm_mma<false>, cudaFuncAttributeMaxDynamicSharedMemorySize, MMA_SMEM);
    cudaFuncSetAttribute(k_gemm_mma<true>,  cudaFuncAttributeMaxDynamicSharedMemorySize, MMA_SMEM);

    k_weff<<<128, 256>>>(Wq, Wk, bq, aw);
    k_prepv<<<dim3(32, 16, B), 256>>>(v_in, 0);
    k_prepv<<<dim3(32, 16, B), 256>>>(v_in, 1);
    k_sqk<<<dim3(M / 32, 2), 256, SQK_SMEM>>>(q_in, k_in);
    k_psimat<<<dim3(LSEQ / 256, B * HEADS), 256>>>();
    // P[b] (512 x 1024) = Psi_b @ v_b   (HMMA+ldmatrix, K = 1024)
    k_gemm_mma<false><<<dim3(8, 4, B), 256, MMA_SMEM>>>(
        p_Psih, p_Psil, p_VTh, p_VTl, nullptr, p_P,
        1024, (size_t)512 * 1024, (size_t)1024 * 1024, (size_t)512 * 1024);
    k_phiq<<<dim3(LSEQ / 16, B), 256>>>();
    k_Tp<<<dim3(4, B * HEADS), 256>>>(Wv);
    k_U<<<dim3(4, B * HEADS), 256, KU_SMEM>>>(Wp);
    // out[b] (1024 x 1024) = Phi_b @ U_b + bp   (HMMA+ldmatrix, K = 512)
    k_gemm_mma<true><<<dim3(8, 8, B), 256, MMA_SMEM>>>(
        p_Phih, p_Phil, p_UTh, p_UTl, bp, out,
        512, (size_t)1024 * 512, (size_t)1024 * 512, (size_t)1024 * 1024);
    k_ln<<<M, 256>>>(out, gamma, beta);
}

// round 17
// speedup vs baseline: 1.0718x; 1.0084x over previous
#include <cuda_runtime.h>
#include <cuda_bf16.h>
#include <cstdint>

#define EMBED 1024
#define HEADS 16
#define HDIM  64
#define LSEQ  1024
#define MAXB  4
#define MCH   32
#define OUTD  1024
#define PIF   3.14159265358979f

typedef unsigned long long u64;

// ================= helpers =================
__device__ __forceinline__ float frcp(float x) {
    float r; asm("rcp.approx.f32 %0, %1;" : "=f"(r) : "f"(x)); return r;
}
__device__ __forceinline__ u64 fma2(u64 a, u64 b, u64 c) {
    u64 d;
    asm("fma.rn.f32x2 %0, %1, %2, %3;" : "=l"(d) : "l"(a), "l"(b), "l"(c));
    return d;
}
__device__ __forceinline__ uint32_t smem_u32(const void* p) {
    uint32_t a;
    asm("{ .reg .u64 t; cvta.to.shared.u64 t, %1; cvt.u32.u64 %0, t; }" : "=r"(a) : "l"(p));
    return a;
}
__device__ __forceinline__ void mma16816(float* c, const unsigned* a, const unsigned* b) {
    asm volatile(
        "mma.sync.aligned.m16n8k16.row.col.f32.bf16.bf16.f32 "
        "{%0,%1,%2,%3}, {%4,%5,%6,%7}, {%8,%9}, {%0,%1,%2,%3};"
        : "+f"(c[0]), "+f"(c[1]), "+f"(c[2]), "+f"(c[3])
        : "r"(a[0]), "r"(a[1]), "r"(a[2]), "r"(a[3]), "r"(b[0]), "r"(b[1]));
}
__device__ __forceinline__ void ldsm_x4(unsigned* r, uint32_t addr) {
    asm volatile("ldmatrix.sync.aligned.m8n8.x4.shared.b16 {%0,%1,%2,%3}, [%4];"
        : "=r"(r[0]), "=r"(r[1]), "=r"(r[2]), "=r"(r[3]) : "r"(addr));
}
__device__ __forceinline__ unsigned pack_hi(float x0, float x1) {
    __nv_bfloat162 h;
    h.x = __float2bfloat16(x0);
    h.y = __float2bfloat16(x1);
    return *(unsigned*)&h;
}
__device__ __forceinline__ unsigned pack_lo(float x0, float x1) {
    __nv_bfloat16 h0 = __float2bfloat16(x0);
    __nv_bfloat16 h1 = __float2bfloat16(x1);
    __nv_bfloat162 l;
    l.x = __float2bfloat16(x0 - __bfloat162float(h0));
    l.y = __float2bfloat16(x1 - __bfloat162float(h1));
    return *(unsigned*)&l;
}

// ================= scratch =================
__device__ float g_WqE[EMBED * HEADS];
__device__ float g_WkE[EMBED * HEADS];
__device__ float g_bqE[HEADS];
__device__ float g_SQ[MAXB * HEADS * LSEQ];
__device__ float g_SK[MAXB * HEADS * LSEQ];
__device__ unsigned g_skmax_bits;
__device__ float g_Spart[4 * MAXB * HEADS * MCH];
__device__ float g_P[(size_t)MAXB * 512 * EMBED];
__device__ float g_Tpart[4 * MAXB * HEADS * MCH * HDIM];   // [ec][bn][m][d]

__device__ __align__(16) __nv_bfloat16 g_Psih[(size_t)MAXB * 512 * LSEQ];
__device__ __align__(16) __nv_bfloat16 g_Psil[(size_t)MAXB * 512 * LSEQ];
__device__ __align__(16) __nv_bfloat16 g_VTh[(size_t)MAXB * 1024 * 1024];
__device__ __align__(16) __nv_bfloat16 g_VTl[(size_t)MAXB * 1024 * 1024];
__device__ __align__(16) __nv_bfloat16 g_Phih[(size_t)MAXB * LSEQ * 512];
__device__ __align__(16) __nv_bfloat16 g_Phil[(size_t)MAXB * LSEQ * 512];
__device__ __align__(16) __nv_bfloat16 g_UTh[(size_t)MAXB * 1024 * 512];
__device__ __align__(16) __nv_bfloat16 g_UTl[(size_t)MAXB * 1024 * 512];

// ================= K0a: effective weights =================
__global__ void k_weff(const float* __restrict__ Wq, const float* __restrict__ Wk,
                       const float* __restrict__ bq, const float* __restrict__ aw) {
    int t = blockIdx.x * blockDim.x + threadIdx.x;
    if (t == 0) g_skmax_bits = 0u;
    int side = t >> 14;
    int u = t & 16383;
    int e = u >> 4, n = u & 15;
    const float* W = side ? Wk : Wq;
    const float* w = aw + side * HDIM;
    float s = 0.f;
#pragma unroll 8
    for (int d = 0; d < HDIM; d++)
        s += W[(size_t)e * (HEADS * HDIM) + n * HDIM + d] * w[d];
    if (side) g_WkE[e * 16 + n] = s;
    else      g_WqE[e * 16 + n] = s;
    if (!side && e == 0) {
        float sb = 0.f;
#pragma unroll 8
        for (int d = 0; d < HDIM; d++) sb += bq[n * HDIM + d] * w[d];
        g_bqE[n] = sb;
    }
}

// ================= K0b: V transpose + bf16 split (half grid per launch) ===========
__global__ void __launch_bounds__(256) k_prepv(const float* __restrict__ vin, int half) {
    __shared__ float tsm[32][33];
    int cx = blockIdx.x, cy = blockIdx.y + half * 16, b = blockIdx.z;
    const float* in = vin + (size_t)b * 1024 * 1024;
    __nv_bfloat16* oh = g_VTh + (size_t)b * 1024 * 1024;
    __nv_bfloat16* ol = g_VTl + (size_t)b * 1024 * 1024;
    int r0 = cy * 32, c0 = cx * 32;
    int tx = threadIdx.x & 31, ty = threadIdx.x >> 5;
#pragma unroll
    for (int s = 0; s < 4; s++) {
        int r = ty + s * 8;
        tsm[r][tx] = in[(size_t)(r0 + r) * 1024 + c0 + tx];
    }
    __syncthreads();
#pragma unroll
    for (int s = 0; s < 4; s++) {
        int c = ty + s * 8;
        float x = tsm[tx][c];
        __nv_bfloat16 h = __float2bfloat16(x);
        size_t o = (size_t)(c0 + c) * 1024 + r0 + tx;
        oh[o] = h;
        ol[o] = __float2bfloat16(x - __bfloat162float(h));
    }
}

// ================= K1: sq/sk — 2 rows per thread ==================================
#define PADF 1028
#define SQK_SMEM (16 * PADF * 4)
__global__ void __launch_bounds__(256) k_sqk(const float* __restrict__ qin,
                                             const float* __restrict__ kin) {
    extern __shared__ float sWEt[];
    __shared__ float sred[8];
    int side = blockIdx.y;
    const float* WE = side ? g_WkE : g_WqE;
    int tid = threadIdx.x;

    for (int idx = tid; idx < EMBED * HEADS; idx += 256) {
        int e = idx >> 4, n = idx & 15;
        sWEt[n * PADF + e] = WE[idx];
    }
    __syncthreads();

    int rl = tid >> 3;                 // 0..31
    int p  = tid & 7;
    int rowA = blockIdx.x * 64 + rl;
    int rowB = rowA + 32;
    const float* base = side ? kin : qin;
    const float* xrA = base + (size_t)rowA * EMBED;
    const float* xrB = base + (size_t)rowB * EMBED;

    u64 accA[16], accB[16];
#pragma unroll
    for (int n = 0; n < 16; n++) { accA[n] = 0ull; accB[n] = 0ull; }

#pragma unroll 4
    for (int i = 0; i < 32; i++) {
        int e = (i * 8 + p) * 4;
        float4 xa = *(const float4*)(xrA + e);
        float4 xb = *(const float4*)(xrB + e);
        u64 alo, ahi, blo, bhi;
        asm("mov.b64 %0, {%1, %2};" : "=l"(alo) : "f"(xa.x), "f"(xa.y));
        asm("mov.b64 %0, {%1, %2};" : "=l"(ahi) : "f"(xa.z), "f"(xa.w));
        asm("mov.b64 %0, {%1, %2};" : "=l"(blo) : "f"(xb.x), "f"(xb.y));
        asm("mov.b64 %0, {%1, %2};" : "=l"(bhi) : "f"(xb.z), "f"(xb.w));
#pragma unroll
        for (int n = 0; n < 16; n++) {
            float4 wv = *(const float4*)&sWEt[n * PADF + e];
            u64 wlo, whi;
            asm("mov.b64 %0, {%1, %2};" : "=l"(wlo) : "f"(wv.x), "f"(wv.y));
            asm("mov.b64 %0, {%1, %2};" : "=l"(whi) : "f"(wv.z), "f"(wv.w));
            accA[n] = fma2(alo, wlo, accA[n]);
            accA[n] = fma2(ahi, whi, accA[n]);
            accB[n] = fma2(blo, wlo, accB[n]);
            accB[n] = fma2(bhi, whi, accB[n]);
        }
    }

    float sA[16], sB[16];
#pragma unroll
    for (int n = 0; n < 16; n++) {
        float lo, hi;
        asm("mov.b64 {%0, %1}, %2;" : "=f"(lo), "=f"(hi) : "l"(accA[n]));
        sA[n] = lo + hi;
        asm("mov.b64 {%0, %1}, %2;" : "=f"(lo), "=f"(hi) : "l"(accB[n]));
        sB[n] = lo + hi;
    }
#pragma unroll
    for (int msk = 1; msk < 8; msk <<= 1)
#pragma unroll
        for (int n = 0; n < 16; n++) {
            sA[n] += __shfl_xor_sync(0xffffffffu, sA[n], msk);
            sB[n] += __shfl_xor_sync(0xffffffffu, sB[n], msk);
        }

    int n0 = p * 2;
    float vA0 = sA[n0], vA1 = sA[n0 + 1];
    float vB0 = sB[n0], vB1 = sB[n0 + 1];
    if (!side) {
        float b0 = g_bqE[n0], b1 = g_bqE[n0 + 1];
        vA0 += b0; vA1 += b1; vB0 += b0; vB1 += b1;
    }
    float* dst = side ? g_SK : g_SQ;
    {
        int b = rowA >> 10, ii = rowA & 1023;
        dst[((b * 16 + n0) << 10) + ii]     = vA0;
        dst[((b * 16 + n0 + 1) << 10) + ii] = vA1;
    }
    {
        int b = rowB >> 10, ii = rowB & 1023;
        dst[((b * 16 + n0) << 10) + ii]     = vB0;
        dst[((b * 16 + n0 + 1) << 10) + ii] = vB1;
    }

    if (side) {
        float a = fmaxf(fmaxf(fabsf(vA0), fabsf(vA1)), fmaxf(fabsf(vB0), fabsf(vB1)));
        int lane = tid & 31, wid = tid >> 5;
#pragma unroll
        for (int o = 16; o; o >>= 1) a = fmaxf(a, __shfl_xor_sync(0xffffffffu, a, o));
        if (lane == 0) sred[wid] = a;
        __syncthreads();
        if (tid == 0) {
            float mx = 0.f;
#pragma unroll
            for (int w2 = 0; w2 < 8; w2++) mx = fmaxf(mx, sred[w2]);
            atomicMax(&g_skmax_bits, __float_as_uint(mx));
        }
    }
}

// ---- inline Chebyshev nodes ----
#define CHEB_LOCAL(yn, wb, tid) do { \
    if ((tid) < MCH) { \
        float smax = __uint_as_float(g_skmax_bits); \
        float Y = smax * 1.0005f + 1e-6f; \
        float th = (2.f * (tid) + 1.f) * (PIF / 64.f); \
        (yn)[tid] = Y * cosf(th); \
        if (wb) ((float*)(wb))[tid] = (((tid) & 1) ? -sinf(th) : sinf(th)); \
    } \
} while (0)

// ================= K2: Psi + S partials =================
__global__ void __launch_bounds__(256) k_psimat() {
    __shared__ float sp[256][33];
    __shared__ float colsum[8][32];
    __shared__ float yn[MCH], wb[MCH];
    int bn = blockIdx.y;
    int b = bn >> 4, n = bn & 15;
    int jc = blockIdx.x;
    int j0 = jc * 256;
    int tid = threadIdx.x;
    CHEB_LOCAL(yn, wb, tid);
    __syncthreads();

    {
        float y = g_SK[(bn << 10) + j0 + tid];
        float t[MCH];
        float den = 0.f;
#pragma unroll
        for (int m = 0; m < MCH; m++) {
            float d = y - yn[m];
            d = (fabsf(d) < 1e-12f) ? 1e-12f : d;
            t[m] = wb[m] * frcp(d);
            den += t[m];
        }
        float ri = frcp(den);
#pragma unroll
        for (int m = 0; m < MCH; m++) sp[tid][m] = t[m] * ri;
    }
    __syncthreads();

    {
        int m = tid & 31, seg = tid >> 5;
        float s = 0.f;
#pragma unroll 8
        for (int r = 0; r < 32; r++) s += sp[seg * 32 + r][m];
        colsum[seg][m] = s;
    }
    __syncthreads();
    if (tid < 32) {
        float t = 0.f;
#pragma unroll
        for (int s8 = 0; s8 < 8; s8++) t += colsum[s8][tid];
        g_Spart[(jc * 64 + bn) * MCH + tid] = t;
    }

    int r  = tid >> 3;
    int cg = (tid & 7) * 32;
    size_t base = (((size_t)b * 512) + n * 32 + r) * LSEQ + j0 + cg;
#pragma unroll
    for (int q8 = 0; q8 < 4; q8++) {
        unsigned hh[4], ll[4];
#pragma unroll
        for (int p2 = 0; p2 < 4; p2++) {
            float x0 = sp[cg + q8 * 8 + p2 * 2][r];
            float x1 = sp[cg + q8 * 8 + p2 * 2 + 1][r];
            hh[p2] = pack_hi(x0, x1);
            ll[p2] = pack_lo(x0, x1);
        }
        *(uint4*)(g_Psih + base + q8 * 8) = *(uint4*)hh;
        *(uint4*)(g_Psil + base + q8 * 8) = *(uint4*)ll;
    }
}

// ================= HMMA bf16-split GEMM — 3-stage cp.async + ldmatrix =============
#define BKC 64
#define STRD 72
#define STRDB (STRD * 2)
#define TEN_ELE (128 * STRD)
#define STAGE_ELE (4 * TEN_ELE)
#define NSTAGE 3
#define MMA_SMEM (NSTAGE * STAGE_ELE * 2)

template <bool BIAS>
__global__ void __launch_bounds__(256) k_gemm_mma(
    const __nv_bfloat16* __restrict__ Ah, const __nv_bfloat16* __restrict__ Al,
    const __nv_bfloat16* __restrict__ Bh, const __nv_bfloat16* __restrict__ Bl,
    const float* __restrict__ bias, float* __restrict__ C,
    int K, size_t sA, size_t sB, size_t sC)
{
    extern __shared__ __nv_bfloat16 sm[];
    uint32_t sbase = smem_u32(sm);

    int tid = threadIdx.x, lane = tid & 31, wid = tid >> 5;
    int wm = wid >> 1, wn = wid & 1;
    int m0 = blockIdx.y * 128, n0 = blockIdx.x * 128;

    const __nv_bfloat16* srcs[4] = {
        Ah + blockIdx.z * sA + (size_t)m0 * K,
        Al + blockIdx.z * sA + (size_t)m0 * K,
        Bh + blockIdx.z * sB + (size_t)n0 * K,
        Bl + blockIdx.z * sB + (size_t)n0 * K };
    C += blockIdx.z * sC;

    int g = lane >> 2, tg = lane & 3;
    const int nch = K >> 6;

    int lam = lane & 15;
    int lakB = (lane & 16) ? 16 : 0;
    int lbn = (lane & 7) + ((lane & 16) ? 8 : 0);
    int lbkB = (lane & 8) ? 16 : 0;

    float acc[2][8][4];
#pragma unroll
    for (int a = 0; a < 2; a++)
#pragma unroll
        for (int b = 0; b < 8; b++)
#pragma unroll
            for (int c = 0; c < 4; c++) acc[a][b][c] = 0.f;

    auto load_stage = [&](int st, int c) {
#pragma unroll
        for (int t = 0; t < 4; t++) {
#pragma unroll
            for (int s = 0; s < 4; s++) {
                int i = tid + s * 256;
                int row = i >> 3, ch = (i & 7) * 8;
                const void* gp = srcs[t] + (size_t)row * K + c * BKC + ch;
                uint32_t dp = sbase + (uint32_t)(st * STAGE_ELE + t * TEN_ELE + row * STRD + ch) * 2;
                asm volatile("cp.async.cg.shared.global [%0], [%1], 16;" :: "r"(dp), "l"(gp));
            }
        }
        asm volatile("cp.async.commit_group;");
    };

    load_stage(0, 0);
    if (nch > 1) load_stage(1, 1);

    for (int c = 0; c < nch; c++) {
        if (c + 1 < nch) {
            asm volatile("cp.async.wait_group 1;");
        } else {
            asm volatile("cp.async.wait_group 0;");
        }
        __syncthreads();

        if (c + 2 < nch) load_stage((c + 2) % NSTAGE, c + 2);

        uint32_t sb = sbase + (uint32_t)((c % NSTAGE) * STAGE_ELE) * 2;
        uint32_t aAh = sb + (uint32_t)(wm * 32 + lam) * STRDB + lakB;
        uint32_t aAl = aAh + TEN_ELE * 2;
        uint32_t aBh = sb + 2u * TEN_ELE * 2 + (uint32_t)(wn * 64 + lbn) * STRDB + lbkB;
        uint32_t aBl = aBh + TEN_ELE * 2;

#pragma unroll
        for (int ks = 0; ks < 4; ks++) {
            unsigned ah0[4], ah1[4], al0[4], al1[4];
            ldsm_x4(ah0, aAh + ks * 32);
            ldsm_x4(ah1, aAh + 16 * STRDB + ks * 32);
            ldsm_x4(al0, aAl + ks * 32);
            ldsm_x4(al1, aAl + 16 * STRDB + ks * 32);
#pragma unroll
            for (int ntp = 0; ntp < 4; ntp++) {
                unsigned bh[4], bl[4];
                ldsm_x4(bh, aBh + ntp * 16 * STRDB + ks * 32);
                ldsm_x4(bl, aBl + ntp * 16 * STRDB + ks * 32);
                int nt = 2 * ntp;
                mma16816(acc[0][nt],     ah0, bh);
                mma16816(acc[0][nt + 1], ah0, bh + 2);
                mma16816(acc[1][nt],     ah1, bh);
                mma16816(acc[1][nt + 1], ah1, bh + 2);
                mma16816(acc[0][nt],     ah0, bl);
                mma16816(acc[0][nt + 1], ah0, bl + 2);
                mma16816(acc[1][nt],     ah1, bl);
                mma16816(acc[1][nt + 1], ah1, bl + 2);
                mma16816(acc[0][nt],     al0, bh);
                mma16816(acc[0][nt + 1], al0, bh + 2);
                mma16816(acc[1][nt],     al1, bh);
                mma16816(acc[1][nt + 1], al1, bh + 2);
            }
        }
        __syncthreads();
    }

#pragma unroll
    for (int mt = 0; mt < 2; mt++) {
        int row0 = m0 + wm * 32 + mt * 16 + g;
#pragma unroll
        for (int nt = 0; nt < 8; nt++) {
            int col = n0 + wn * 64 + nt * 8 + tg * 2;
            float2 v0, v1;
            v0.x = acc[mt][nt][0]; v0.y = acc[mt][nt][1];
            v1.x = acc[mt][nt][2]; v1.y = acc[mt][nt][3];
            if (BIAS) {
                float2 bv = *(const float2*)(bias + col);
                v0.x += bv.x; v0.y += bv.y;
                v1.x += bv.x; v1.y += bv.y;
            }
            *(float2*)(C + (size_t)row0 * 1024 + col) = v0;
            *(float2*)(C + (size_t)(row0 + 8) * 1024 + col) = v1;
        }
    }
}

// ================= K4: T partials — grid (4 echunks, 64 bn), conflict-free ========
__global__ void __launch_bounds__(256) k_Tp(const float* __restrict__ Wv) {
    __shared__ float sp[32 * 68];
    __shared__ float sw[64 * 64];
    int ec = blockIdx.x;
    int bn = blockIdx.y;
    int b = bn >> 4, n = bn & 15;
    int tid = threadIdx.x;
    int m = tid >> 3;
    int p = tid & 7;

    const float* P = g_P + ((size_t)b * 512 + n * 32) * EMBED + ec * 256;

    float acc[8];
#pragma unroll
    for (int c = 0; c < 8; c++) acc[c] = 0.f;

    for (int e0 = 0; e0 < 256; e0 += 64) {
        __syncthreads();
#pragma unroll
        for (int s = 0; s < 2; s++) {
            int f4 = tid + s * 256;
            int row = f4 >> 4, c4 = (f4 & 15) * 4;
            *(float4*)&sp[row * 68 + c4] = *(const float4*)(P + (size_t)row * EMBED + e0 + c4);
        }
#pragma unroll
        for (int s = 0; s < 4; s++) {
            int f4 = tid + s * 256;
            int row = f4 >> 4, c4 = (f4 & 15) * 4;
            *(float4*)&sw[row * 64 + c4] =
                *(const float4*)(Wv + (size_t)(ec * 256 + e0 + row) * (HEADS * HDIM) + n * 64 + c4);
        }
        __syncthreads();

#pragma unroll 4
        for (int e = 0; e < 64; e++) {
            float pv = sp[m * 68 + e];
            float4 w0 = *(const float4*)&sw[e * 64 + 4 * p];
            float4 w1 = *(const float4*)&sw[e * 64 + 32 + 4 * p];
            acc[0] += pv * w0.x; acc[1] += pv * w0.y;
            acc[2] += pv * w0.z; acc[3] += pv * w0.w;
            acc[4] += pv * w1.x; acc[5] += pv * w1.y;
            acc[6] += pv * w1.z; acc[7] += pv * w1.w;
        }
    }

    float* Tp = g_Tpart + (((size_t)ec * 64 + bn) * 32 + m) * 64;
    float4 o0, o1;
    o0.x = acc[0]; o0.y = acc[1]; o0.z = acc[2]; o0.w = acc[3];
    o1.x = acc[4]; o1.y = acc[5]; o1.z = acc[6]; o1.w = acc[7];
    *(float4*)(Tp + 4 * p) = o0;
    *(float4*)(Tp + 32 + 4 * p) = o1;
}

// ================= K5: U (sums T partials) + transpose/bf16 split -> UT ===========
#define KU_SMEM ((32 * 68 + 16 * 256 + 32 * 264) * 4)
__global__ void __launch_bounds__(256) k_U(const float* __restrict__ Wp) {
    extern __shared__ float us[];
    float* sT = us;
    float* sW = us + 32 * 68;
    float* sO = us + 32 * 68 + 16 * 256;

    int bn = blockIdx.y;
    int b = bn >> 4, n = bn & 15;
    int c0 = blockIdx.x * 256;
    int tid = threadIdx.x;
    int m = tid >> 3;
    int p = tid & 7;
    int dq4 = 4 * p;

#pragma unroll
    for (int s = 0; s < 2; s++) {
        int f4 = tid + s * 256;
        int row = f4 >> 4, c4 = (f4 & 15) * 4;
        size_t off = ((size_t)bn * 32 + row) * 64 + c4;
        float4 a0 = *(const float4*)(g_Tpart + off);
        float4 a1 = *(const float4*)(g_Tpart + (size_t)1 * 64 * 32 * 64 + off);
        float4 a2 = *(const float4*)(g_Tpart + (size_t)2 * 64 * 32 * 64 + off);
        float4 a3 = *(const float4*)(g_Tpart + (size_t)3 * 64 * 32 * 64 + off);
        float4 o;
        o.x = (a0.x + a1.x) + (a2.x + a3.x);
        o.y = (a0.y + a1.y) + (a2.y + a3.y);
        o.z = (a0.z + a1.z) + (a2.z + a3.z);
        o.w = (a0.w + a1.w) + (a2.w + a3.w);
        *(float4*)&sT[row * 68 + c4] = o;
    }

    float acc[32];
#pragma unroll
    for (int c = 0; c < 32; c++) acc[c] = 0.f;

    for (int dt = 0; dt < 4; dt++) {
        __syncthreads();
#pragma unroll
        for (int s = 0; s < 4; s++) {
            int f4 = tid + s * 256;
            int row = f4 >> 6, c4 = (f4 & 63) * 4;
            *(float4*)&sW[row * 256 + c4] =
                *(const float4*)(Wp + (size_t)(n * 64 + dt * 16 + row) * OUTD + c0 + c4);
        }
        __syncthreads();

#pragma unroll
        for (int d = 0; d < 16; d++) {
            float t = sT[m * 68 + dt * 16 + d];
#pragma unroll
            for (int k = 0; k < 8; k++) {
                float4 w = *(const float4*)&sW[d * 256 + k * 32 + dq4];
                acc[k * 4 + 0] += t * w.x;
                acc[k * 4 + 1] += t * w.y;
                acc[k * 4 + 2] += t * w.z;
                acc[k * 4 + 3] += t * w.w;
            }
        }
    }

#pragma unroll
    for (int k = 0; k < 8; k++) {
        float4 o;
        o.x = acc[k * 4 + 0]; o.y = acc[k * 4 + 1];
        o.z = acc[k * 4 + 2]; o.w = acc[k * 4 + 3];
        *(float4*)&sO[m * 264 + k * 32 + dq4] = o;
    }
    __syncthreads();

    {
        int o = c0 + tid;
        size_t rowbase = (((size_t)b * 1024) + o) * 512 + n * 32;
        unsigned hh[16], ll[16];
#pragma unroll
        for (int mm = 0; mm < 16; mm++) {
            float x0 = sO[(2 * mm) * 264 + tid];
            float x1 = sO[(2 * mm + 1) * 264 + tid];
            hh[mm] = pack_hi(x0, x1);
            ll[mm] = pack_lo(x0, x1);
        }
#pragma unroll
        for (int q = 0; q < 4; q++) {
            *(uint4*)(g_UTh + rowbase + q * 8) = *(uint4*)&hh[q * 4];
            *(uint4*)(g_UTl + rowbase + q * 8) = *(uint4*)&ll[q * 4];
        }
    }
}

// ================= K6: Phi~ (bf16 hi/lo, [i][nm]) =================
__global__ void __launch_bounds__(256) k_phiq() {
    __shared__ float syn[MCH];
    __shared__ float sS[16][MCH];
    int b = blockIdx.y;
    int tid = threadIdx.x;
    int n = tid & 15;
    int ir = tid >> 4;
    int i = blockIdx.x * 16 + ir;

    CHEB_LOCAL(syn, (float*)0, tid);
    for (int t = tid; t < 16 * MCH; t += 256) {
        int hn = t >> 5, m = t & 31;
        int bn = b * 16 + hn;
        float s = g_Spart[(0 * 64 + bn) * MCH + m] + g_Spart[(1 * 64 + bn) * MCH + m]
                + g_Spart[(2 * 64 + bn) * MCH + m] + g_Spart[(3 * 64 + bn) * MCH + m];
        sS[hn][m] = s;
    }
    __syncthreads();

    float sq = g_SQ[((b * 16 + n) << 10) + i];
    float phi[MCH];
    float den = 0.f;
#pragma unroll
    for (int m = 0; m < MCH; m++) {
        float u = __expf(2.f * (sq + syn[m]));
        float t = (u - 1.f) * frcp(u + 1.f);
        float p = __expf(t);
        phi[m] = p;
        den += p * sS[n][m];
    }
    float inv = frcp(den);

    size_t base = ((((size_t)b << 10) + i) * 512) + n * 32;
#pragma unroll
    for (int q8 = 0; q8 < 4; q8++) {
        unsigned hh[4], ll[4];
#pragma unroll
        for (int p2 = 0; p2 < 4; p2++) {
            float x0 = phi[q8 * 8 + p2 * 2]     * inv;
            float x1 = phi[q8 * 8 + p2 * 2 + 1] * inv;
            hh[p2] = pack_hi(x0, x1);
            ll[p2] = pack_lo(x0, x1);
        }
        *(uint4*)(g_Phih + base + q8 * 8) = *(uint4*)hh;
        *(uint4*)(g_Phil + base + q8 * 8) = *(uint4*)ll;
    }
}

// ================= K7: layernorm =================
__global__ void __launch_bounds__(256) k_ln(float* __restrict__ y,
                                            const float* __restrict__ gamma,
                                            const float* __restrict__ beta) {
    int row = blockIdx.x, tid = threadIdx.x;
    float4* yp = (float4*)(y + (size_t)row * 1024);
    float4 v = yp[tid];
    float s  = v.x + v.y + v.z + v.w;
    float ss = v.x * v.x + v.y * v.y + v.z * v.z + v.w * v.w;

    __shared__ float red[16];
    int lane = tid & 31, wid = tid >> 5;
#pragma unroll
    for (int o = 16; o; o >>= 1) {
        s  += __shfl_xor_sync(0xffffffffu, s,  o);
        ss += __shfl_xor_sync(0xffffffffu, ss, o);
    }
    if (lane == 0) { red[wid] = s; red[wid + 8] = ss; }
    __syncthreads();
    if (tid == 0) {
        float S = 0.f, SS = 0.f;
        for (int w = 0; w < 8; w++) { S += red[w]; SS += red[w + 8]; }
        red[0] = S; red[1] = SS;
    }
    __syncthreads();
    float mean = red[0] * (1.0f / 1024.0f);
    float var  = red[1] * (1.0f / 1024.0f) - mean * mean;
    float rr = rsqrtf(var + 1e-6f);

    float4 g  = ((const float4*)gamma)[tid];
    float4 bb = ((const float4*)beta)[tid];
    float4 o;
    o.x = (v.x - mean) * rr * g.x + bb.x;
    o.y = (v.y - mean) * rr * g.y + bb.y;
    o.z = (v.z - mean) * rr * g.z + bb.z;
    o.w = (v.w - mean) * rr * g.w + bb.w;
    yp[tid] = o;
}

// ================= launcher =================
extern "C" void kernel_launch(void* const* d_in, const int* in_sizes, int n_in,
                              void* d_out, int out_size) {
    (void)n_in; (void)out_size;
    const float* k_in  = (const float*)d_in[0];
    const float* q_in  = (const float*)d_in[1];
    const float* v_in  = (const float*)d_in[2];
    const float* Wq    = (const float*)d_in[3];
    const float* bq    = (const float*)d_in[4];
    const float* Wk    = (const float*)d_in[5];
    const float* Wv    = (const float*)d_in[6];
    const float* Wp    = (const float*)d_in[7];
    const float* bp    = (const float*)d_in[8];
    const float* aw    = (const float*)d_in[9];
    const float* gamma = (const float*)d_in[10];
    const float* beta  = (const float*)d_in[11];
    float* out = (float*)d_out;

    int B = in_sizes[0] / (LSEQ * EMBED);   // 4
    int M = B * LSEQ;                        // 4096

    float* p_P = nullptr;
    __nv_bfloat16 *p_Psih, *p_Psil, *p_VTh, *p_VTl, *p_Phih, *p_Phil, *p_UTh, *p_UTl;
    cudaGetSymbolAddress((void**)&p_P,    g_P);
    cudaGetSymbolAddress((void**)&p_Psih, g_Psih);
    cudaGetSymbolAddress((void**)&p_Psil, g_Psil);
    cudaGetSymbolAddress((void**)&p_VTh,  g_VTh);
    cudaGetSymbolAddress((void**)&p_VTl,  g_VTl);
    cudaGetSymbolAddress((void**)&p_Phih, g_Phih);
    cudaGetSymbolAddress((void**)&p_Phil, g_Phil);
    cudaGetSymbolAddress((void**)&p_UTh,  g_UTh);
    cudaGetSymbolAddress((void**)&p_UTl,  g_UTl);

    cudaFuncSetAttribute(k_sqk, cudaFuncAttributeMaxDynamicSharedMemorySize, SQK_SMEM);
    cudaFuncSetAttribute(k_U,   cudaFuncAttributeMaxDynamicSharedMemorySize, KU_SMEM);
    cudaFuncSetAttribute(k_gemm_mma<false>, cudaFuncAttributeMaxDynamicSharedMemorySize, MMA_SMEM);
    cudaFuncSetAttribute(k_gemm_mma<true>,  cudaFuncAttributeMaxDynamicSharedMemorySize, MMA_SMEM);

    k_weff<<<128, 256>>>(Wq, Wk, bq, aw);
    k_prepv<<<dim3(32, 16, B), 256>>>(v_in, 0);
    k_prepv<<<dim3(32, 16, B), 256>>>(v_in, 1);
    k_sqk<<<dim3(M / 64, 2), 256, SQK_SMEM>>>(q_in, k_in);   // 2 rows/thread
    k_psimat<<<dim3(LSEQ / 256, B * HEADS), 256>>>();
    // P[b] (512 x 1024) = Psi_b @ v_b   (HMMA+ldmatrix, K = 1024)
    k_gemm_mma<false><<<dim3(8, 4, B), 256, MMA_SMEM>>>(
        p_Psih, p_Psil, p_VTh, p_VTl, nullptr, p_P,
        1024, (size_t)512 * 1024, (size_t)1024 * 1024, (size_t)512 * 1024);
    k_phiq<<<dim3(LSEQ / 16, B), 256>>>();
    k_Tp<<<dim3(4, B * HEADS), 256>>>(Wv);
    k_U<<<dim3(4, B * HEADS), 256, KU_SMEM>>>(Wp);
    // out[b] (1024 x 1024) = Phi_b @ U_b + bp   (HMMA+ldmatrix, K = 512)
    k_gemm_mma<true><<<dim3(8, 8, B), 256, MMA_SMEM>>>(
        p_Phih, p_Phil, p_UTh, p_UTl, bp, out,
        512, (size_t)1024 * 512, (size_t)1024 * 512, (size_t)1024 * 1024);
    k_ln<<<M, 256>>>(out, gamma, beta);
}